// round 1
// baseline (speedup 1.0000x reference)
#include <cuda_runtime.h>
#include <cuda_bf16.h>
#include <math.h>

// ---------------- problem constants ----------------
#define B_    2
#define S_    2048
#define DIM_  2048
#define NH_   16
#define HD_   128
#define HID_  5632
#define M_    (B_*S_)          // 4096 rows
#define EPS_  1e-5f
#define SCALE_ 0.08838834764831845f   // 1/sqrt(128)

// ---------------- scratch (device globals; no allocation) ----------------
__device__ float g_h  [(size_t)M_*DIM_];
__device__ float g_q  [(size_t)M_*DIM_];
__device__ float g_k  [(size_t)M_*DIM_];
__device__ float g_v  [(size_t)M_*DIM_];
__device__ float g_att[(size_t)M_*DIM_];
__device__ float g_h1 [(size_t)M_*DIM_];
__device__ float g_f  [(size_t)M_*DIM_];
__device__ float g_t1 [(size_t)M_*HID_];
__device__ float g_t3 [(size_t)M_*HID_];
__device__ float g_scores[(size_t)B_*NH_*S_*S_];

// ---------------- rmsnorm ----------------
__global__ __launch_bounds__(256) void rmsnorm_k(const float* __restrict__ x,
                                                 const float* __restrict__ w,
                                                 float* __restrict__ o)
{
    __shared__ float red[8];
    const size_t row = blockIdx.x;
    const float* xr = x + row * (size_t)DIM_;
    const int tid = threadIdx.x;
    float4 v0 = *(const float4*)(xr + tid*4);
    float4 v1 = *(const float4*)(xr + 1024 + tid*4);
    float s = v0.x*v0.x + v0.y*v0.y + v0.z*v0.z + v0.w*v0.w
            + v1.x*v1.x + v1.y*v1.y + v1.z*v1.z + v1.w*v1.w;
    #pragma unroll
    for (int off = 16; off > 0; off >>= 1) s += __shfl_xor_sync(0xffffffffu, s, off);
    if ((tid & 31) == 0) red[tid >> 5] = s;
    __syncthreads();
    s = red[0]+red[1]+red[2]+red[3]+red[4]+red[5]+red[6]+red[7];
    const float r = rsqrtf(s * (1.0f/DIM_) + EPS_);
    float4 w0 = *(const float4*)(w + tid*4);
    float4 w1 = *(const float4*)(w + 1024 + tid*4);
    float* orow = o + row * (size_t)DIM_;
    float4 o0 = make_float4(v0.x*r*w0.x, v0.y*r*w0.y, v0.z*r*w0.z, v0.w*r*w0.w);
    float4 o1 = make_float4(v1.x*r*w1.x, v1.y*r*w1.y, v1.z*r*w1.z, v1.w*r*w1.w);
    *(float4*)(orow + tid*4) = o0;
    *(float4*)(orow + 1024 + tid*4) = o1;
}

// ---------------- generic SGEMM: C[M,N] = A[M,K] * W[N,K]^T (+R) ----------------
// grid: (N/128, M/128), 256 threads, 128x128x8 tiles, 8x8 microtile per thread.
__global__ __launch_bounds__(256) void sgemm_nt(const float* __restrict__ A,
                                                const float* __restrict__ W,
                                                const float* __restrict__ R,
                                                float* __restrict__ C,
                                                int N, int K)
{
    __shared__ float As[8][128];
    __shared__ float Ws[8][128];
    const int tid = threadIdx.x;
    const int bm = blockIdx.y * 128;
    const int bn = blockIdx.x * 128;
    const int lr = tid >> 1;
    const int lc = (tid & 1) << 2;
    const int tx = tid & 15;
    const int ty = tid >> 4;
    const float* Ap = A + (size_t)(bm + lr) * K + lc;
    const float* Wp = W + (size_t)(bn + lr) * K + lc;
    float acc[8][8] = {};
    for (int k0 = 0; k0 < K; k0 += 8) {
        const float4 av = *(const float4*)(Ap + k0);
        const float4 wv = *(const float4*)(Wp + k0);
        __syncthreads();
        As[lc+0][lr]=av.x; As[lc+1][lr]=av.y; As[lc+2][lr]=av.z; As[lc+3][lr]=av.w;
        Ws[lc+0][lr]=wv.x; Ws[lc+1][lr]=wv.y; Ws[lc+2][lr]=wv.z; Ws[lc+3][lr]=wv.w;
        __syncthreads();
        #pragma unroll
        for (int kk = 0; kk < 8; kk++) {
            float a[8], b[8];
            *(float4*)(a)   = *(const float4*)(&As[kk][ty*4]);
            *(float4*)(a+4) = *(const float4*)(&As[kk][64 + ty*4]);
            *(float4*)(b)   = *(const float4*)(&Ws[kk][tx*4]);
            *(float4*)(b+4) = *(const float4*)(&Ws[kk][64 + tx*4]);
            #pragma unroll
            for (int i = 0; i < 8; i++)
                #pragma unroll
                for (int j = 0; j < 8; j++)
                    acc[i][j] = fmaf(a[i], b[j], acc[i][j]);
        }
    }
    #pragma unroll
    for (int i = 0; i < 8; i++) {
        const int m = bm + ((i < 4) ? (ty*4 + i) : (64 + ty*4 + (i-4)));
        float* Crow = C + (size_t)m * N;
        const int c0 = bn + tx*4, c1 = bn + 64 + tx*4;
        float4 v0 = make_float4(acc[i][0], acc[i][1], acc[i][2], acc[i][3]);
        float4 v1 = make_float4(acc[i][4], acc[i][5], acc[i][6], acc[i][7]);
        if (R) {
            const float* Rrow = R + (size_t)m * N;
            float4 r0 = *(const float4*)(Rrow + c0);
            float4 r1 = *(const float4*)(Rrow + c1);
            v0.x += r0.x; v0.y += r0.y; v0.z += r0.z; v0.w += r0.w;
            v1.x += r1.x; v1.y += r1.y; v1.z += r1.z; v1.w += r1.w;
        }
        *(float4*)(Crow + c0) = v0;
        *(float4*)(Crow + c1) = v1;
    }
}

// ---------------- scores = Q*K^T/sqrt(d) + bias + mask ----------------
// grid: (S/128, S/128, B*NH), 256 threads. K-dim = 128, lda = DIM_.
__global__ __launch_bounds__(256) void scores_k(const float* __restrict__ bias,
                                                const float* __restrict__ mask)
{
    __shared__ float As[8][128];
    __shared__ float Ws[8][128];
    const int tid = threadIdx.x;
    const int z = blockIdx.z;
    const int b = z >> 4;
    const int h = z & 15;
    const int bm = blockIdx.y * 128;   // q tile
    const int bn = blockIdx.x * 128;   // k tile
    const int lr = tid >> 1;
    const int lc = (tid & 1) << 2;
    const int tx = tid & 15;
    const int ty = tid >> 4;
    const float* Ap = g_q + (size_t)b*S_*DIM_ + (size_t)(bm + lr)*DIM_ + h*HD_ + lc;
    const float* Wp = g_k + (size_t)b*S_*DIM_ + (size_t)(bn + lr)*DIM_ + h*HD_ + lc;
    float acc[8][8] = {};
    for (int k0 = 0; k0 < HD_; k0 += 8) {
        const float4 av = *(const float4*)(Ap + k0);
        const float4 wv = *(const float4*)(Wp + k0);
        __syncthreads();
        As[lc+0][lr]=av.x; As[lc+1][lr]=av.y; As[lc+2][lr]=av.z; As[lc+3][lr]=av.w;
        Ws[lc+0][lr]=wv.x; Ws[lc+1][lr]=wv.y; Ws[lc+2][lr]=wv.z; Ws[lc+3][lr]=wv.w;
        __syncthreads();
        #pragma unroll
        for (int kk = 0; kk < 8; kk++) {
            float a[8], bb[8];
            *(float4*)(a)    = *(const float4*)(&As[kk][ty*4]);
            *(float4*)(a+4)  = *(const float4*)(&As[kk][64 + ty*4]);
            *(float4*)(bb)   = *(const float4*)(&Ws[kk][tx*4]);
            *(float4*)(bb+4) = *(const float4*)(&Ws[kk][64 + tx*4]);
            #pragma unroll
            for (int i = 0; i < 8; i++)
                #pragma unroll
                for (int j = 0; j < 8; j++)
                    acc[i][j] = fmaf(a[i], bb[j], acc[i][j]);
        }
    }
    float* Cp = g_scores + (size_t)z*S_*S_;
    #pragma unroll
    for (int i = 0; i < 8; i++) {
        const int m = bm + ((i < 4) ? (ty*4 + i) : (64 + ty*4 + (i-4)));
        const int c0 = bn + tx*4, c1 = bn + 64 + tx*4;
        const float* brow = bias + ((size_t)h*S_ + m)*S_;
        const float* mrow = mask + (size_t)m*S_;
        float4 b0 = *(const float4*)(brow + c0);
        float4 b1 = *(const float4*)(brow + c1);
        float4 k0v = *(const float4*)(mrow + c0);
        float4 k1v = *(const float4*)(mrow + c1);
        float4 v0 = make_float4(acc[i][0]*SCALE_ + b0.x + k0v.x,
                                acc[i][1]*SCALE_ + b0.y + k0v.y,
                                acc[i][2]*SCALE_ + b0.z + k0v.z,
                                acc[i][3]*SCALE_ + b0.w + k0v.w);
        float4 v1 = make_float4(acc[i][4]*SCALE_ + b1.x + k1v.x,
                                acc[i][5]*SCALE_ + b1.y + k1v.y,
                                acc[i][6]*SCALE_ + b1.z + k1v.z,
                                acc[i][7]*SCALE_ + b1.w + k1v.w);
        float* Crow = Cp + (size_t)m*S_;
        *(float4*)(Crow + c0) = v0;
        *(float4*)(Crow + c1) = v1;
    }
}

// ---------------- softmax over last dim of scores (in place) ----------------
__global__ __launch_bounds__(256) void softmax_k()
{
    __shared__ float red[8];
    const size_t row = blockIdx.x;
    float* p = g_scores + row * (size_t)S_;
    const int tid = threadIdx.x;
    float4 v0 = *(const float4*)(p + tid*4);
    float4 v1 = *(const float4*)(p + 1024 + tid*4);
    float m = fmaxf(fmaxf(fmaxf(v0.x, v0.y), fmaxf(v0.z, v0.w)),
                    fmaxf(fmaxf(v1.x, v1.y), fmaxf(v1.z, v1.w)));
    #pragma unroll
    for (int off = 16; off > 0; off >>= 1) m = fmaxf(m, __shfl_xor_sync(0xffffffffu, m, off));
    if ((tid & 31) == 0) red[tid >> 5] = m;
    __syncthreads();
    m = fmaxf(fmaxf(fmaxf(red[0], red[1]), fmaxf(red[2], red[3])),
              fmaxf(fmaxf(red[4], red[5]), fmaxf(red[6], red[7])));
    __syncthreads();
    v0.x = __expf(v0.x - m); v0.y = __expf(v0.y - m);
    v0.z = __expf(v0.z - m); v0.w = __expf(v0.w - m);
    v1.x = __expf(v1.x - m); v1.y = __expf(v1.y - m);
    v1.z = __expf(v1.z - m); v1.w = __expf(v1.w - m);
    float s = v0.x+v0.y+v0.z+v0.w + v1.x+v1.y+v1.z+v1.w;
    #pragma unroll
    for (int off = 16; off > 0; off >>= 1) s += __shfl_xor_sync(0xffffffffu, s, off);
    if ((tid & 31) == 0) red[tid >> 5] = s;
    __syncthreads();
    s = red[0]+red[1]+red[2]+red[3]+red[4]+red[5]+red[6]+red[7];
    const float inv = 1.0f / s;
    v0.x*=inv; v0.y*=inv; v0.z*=inv; v0.w*=inv;
    v1.x*=inv; v1.y*=inv; v1.z*=inv; v1.w*=inv;
    *(float4*)(p + tid*4) = v0;
    *(float4*)(p + 1024 + tid*4) = v1;
}

// ---------------- out = probs @ V  (NN gemm, N = 128 head dim) ----------------
// grid: (S/128, B*NH), 256 threads.
__global__ __launch_bounds__(256) void pv_k()
{
    __shared__ float As[8][128];
    __shared__ float Bs[8][128];
    const int tid = threadIdx.x;
    const int z = blockIdx.y;
    const int b = z >> 4;
    const int h = z & 15;
    const int bm = blockIdx.x * 128;
    const int lr = tid >> 1;
    const int lc = (tid & 1) << 2;
    const int tx = tid & 15;
    const int ty = tid >> 4;
    const int brow = tid >> 5;          // 0..7
    const int bcol = (tid & 31) << 2;   // 0..124
    const float* Ap = g_scores + (size_t)z*S_*S_ + (size_t)(bm + lr)*S_ + lc;
    const float* Bp = g_v + (size_t)b*S_*DIM_ + h*HD_;
    float acc[8][8] = {};
    for (int k0 = 0; k0 < S_; k0 += 8) {
        const float4 av = *(const float4*)(Ap + k0);
        const float4 bv = *(const float4*)(Bp + (size_t)(k0 + brow)*DIM_ + bcol);
        __syncthreads();
        As[lc+0][lr]=av.x; As[lc+1][lr]=av.y; As[lc+2][lr]=av.z; As[lc+3][lr]=av.w;
        *(float4*)(&Bs[brow][bcol]) = bv;
        __syncthreads();
        #pragma unroll
        for (int kk = 0; kk < 8; kk++) {
            float a[8], bb[8];
            *(float4*)(a)    = *(const float4*)(&As[kk][ty*4]);
            *(float4*)(a+4)  = *(const float4*)(&As[kk][64 + ty*4]);
            *(float4*)(bb)   = *(const float4*)(&Bs[kk][tx*4]);
            *(float4*)(bb+4) = *(const float4*)(&Bs[kk][64 + tx*4]);
            #pragma unroll
            for (int i = 0; i < 8; i++)
                #pragma unroll
                for (int j = 0; j < 8; j++)
                    acc[i][j] = fmaf(a[i], bb[j], acc[i][j]);
        }
    }
    float* Cp = g_att + (size_t)b*S_*DIM_ + h*HD_;
    #pragma unroll
    for (int i = 0; i < 8; i++) {
        const int m = bm + ((i < 4) ? (ty*4 + i) : (64 + ty*4 + (i-4)));
        float* Crow = Cp + (size_t)m*DIM_;
        float4 v0 = make_float4(acc[i][0], acc[i][1], acc[i][2], acc[i][3]);
        float4 v1 = make_float4(acc[i][4], acc[i][5], acc[i][6], acc[i][7]);
        *(float4*)(Crow + tx*4) = v0;
        *(float4*)(Crow + 64 + tx*4) = v1;
    }
}

// ---------------- swiglu: t1 = silu(t1) * t3 ----------------
__global__ __launch_bounds__(256) void swiglu_k()
{
    const size_t i = ((size_t)blockIdx.x * 256 + threadIdx.x) * 4;
    float4 a = *(const float4*)(g_t1 + i);
    float4 c = *(const float4*)(g_t3 + i);
    a.x = a.x / (1.0f + __expf(-a.x)) * c.x;
    a.y = a.y / (1.0f + __expf(-a.y)) * c.y;
    a.z = a.z / (1.0f + __expf(-a.z)) * c.z;
    a.w = a.w / (1.0f + __expf(-a.w)) * c.w;
    *(float4*)(g_t1 + i) = a;
}

// ---------------- launch ----------------
extern "C" void kernel_launch(void* const* d_in, const int* in_sizes, int n_in,
                              void* d_out, int out_size)
{
    (void)in_sizes; (void)n_in; (void)out_size;
    const float* x    = (const float*)d_in[0];
    const float* mask = (const float*)d_in[1];
    const float* bias = (const float*)d_in[2];
    const float* wq   = (const float*)d_in[3];
    const float* wk   = (const float*)d_in[4];
    const float* wv   = (const float*)d_in[5];
    const float* wo   = (const float*)d_in[6];
    const float* w1   = (const float*)d_in[7];
    const float* w2   = (const float*)d_in[8];
    const float* w3   = (const float*)d_in[9];
    const float* anw  = (const float*)d_in[10];
    const float* fnw  = (const float*)d_in[11];
    float* out = (float*)d_out;

    float *h, *q, *k, *v, *att, *h1, *f, *t1, *t3;
    cudaGetSymbolAddress((void**)&h,   g_h);
    cudaGetSymbolAddress((void**)&q,   g_q);
    cudaGetSymbolAddress((void**)&k,   g_k);
    cudaGetSymbolAddress((void**)&v,   g_v);
    cudaGetSymbolAddress((void**)&att, g_att);
    cudaGetSymbolAddress((void**)&h1,  g_h1);
    cudaGetSymbolAddress((void**)&f,   g_f);
    cudaGetSymbolAddress((void**)&t1,  g_t1);
    cudaGetSymbolAddress((void**)&t3,  g_t3);

    const dim3 gDD(DIM_/128, M_/128);   // (16, 32)
    const dim3 gHD(HID_/128, M_/128);   // (44, 32)

    // attention
    rmsnorm_k<<<M_, 256>>>(x, anw, h);
    sgemm_nt<<<gDD, 256>>>(h, wq, nullptr, q, DIM_, DIM_);
    sgemm_nt<<<gDD, 256>>>(h, wk, nullptr, k, DIM_, DIM_);
    sgemm_nt<<<gDD, 256>>>(h, wv, nullptr, v, DIM_, DIM_);
    scores_k<<<dim3(S_/128, S_/128, B_*NH_), 256>>>(bias, mask);
    softmax_k<<<B_*NH_*S_, 256>>>();
    pv_k<<<dim3(S_/128, B_*NH_), 256>>>();
    sgemm_nt<<<gDD, 256>>>(att, wo, x, h1, DIM_, DIM_);   // h1 = x + att @ wo^T

    // FFN
    rmsnorm_k<<<M_, 256>>>(h1, fnw, f);
    sgemm_nt<<<gHD, 256>>>(f, w1, nullptr, t1, HID_, DIM_);
    sgemm_nt<<<gHD, 256>>>(f, w3, nullptr, t3, HID_, DIM_);
    swiglu_k<<<((size_t)M_*HID_)/1024, 256>>>();
    sgemm_nt<<<gDD, 256>>>(t1, w2, h1, out, DIM_, HID_);  // out = h1 + ff @ w2^T
}

// round 3
// speedup vs baseline: 3.8825x; 3.8825x over previous
#include <cuda_runtime.h>
#include <cuda_bf16.h>
#include <math.h>
#include <stdint.h>

// ---------------- problem constants ----------------
#define B_    2
#define S_    2048
#define DIM_  2048
#define NH_   16
#define HD_   128
#define HID_  5632
#define M_    (B_*S_)          // 4096 rows
#define EPS_  1e-5f
#define SCALE_ 0.08838834764831845f   // 1/sqrt(128)

// ---------------- scratch (device globals; no allocation) ----------------
__device__ float g_h   [(size_t)M_*DIM_];
__device__ float g_qkv [(size_t)M_*3*DIM_];          // [m][0:2048 q | 2048:4096 k | 4096:6144 v]
__device__ float g_vt  [(size_t)B_*NH_*HD_*S_];      // [b][h][d][s]
__device__ float g_att [(size_t)M_*DIM_];
__device__ float g_h1  [(size_t)M_*DIM_];
__device__ float g_f   [(size_t)M_*DIM_];
__device__ float g_t13 [(size_t)M_*2*HID_];          // [m][0:5632 w1 | 5632:11264 w3]
__device__ float g_ff  [(size_t)M_*HID_];
__device__ float g_scores[(size_t)B_*NH_*S_*S_];
// tf32-rounded weight copies
__device__ float g_wqkv[(size_t)3*DIM_*DIM_];
__device__ float g_wo  [(size_t)DIM_*DIM_];
__device__ float g_w13 [(size_t)2*HID_*DIM_];
__device__ float g_w2  [(size_t)DIM_*HID_];

// ---------------- helpers ----------------
__device__ __forceinline__ uint32_t smem_u32(const void* p){
    uint32_t a;
    asm("{ .reg .u64 t; cvta.to.shared.u64 t, %1; cvt.u32.u64 %0, t; }" : "=r"(a) : "l"(p));
    return a;
}
__device__ __forceinline__ float to_tf32(float x){
    uint32_t u; asm("cvt.rna.tf32.f32 %0, %1;" : "=r"(u) : "f"(x));
    return __uint_as_float(u);
}
__device__ __forceinline__ uint32_t swz(uint32_t x){ return x ^ ((x >> 3) & 0x70); }
#define CP16(dst, src) asm volatile("cp.async.cg.shared.global [%0], [%1], 16;" :: "r"(dst), "l"(src))

__device__ __forceinline__ void ldsm4(uint32_t* r, uint32_t addr){
    asm volatile("ldmatrix.sync.aligned.m8n8.x4.shared.b16 {%0,%1,%2,%3}, [%4];"
        : "=r"(r[0]),"=r"(r[1]),"=r"(r[2]),"=r"(r[3]) : "r"(addr));
}
__device__ __forceinline__ void mma1688(float* c, const uint32_t* a, const uint32_t* b){
    asm volatile("mma.sync.aligned.m16n8k8.row.col.f32.tf32.tf32.f32 "
        "{%0,%1,%2,%3}, {%4,%5,%6,%7}, {%8,%9}, {%0,%1,%2,%3};"
        : "+f"(c[0]),"+f"(c[1]),"+f"(c[2]),"+f"(c[3])
        : "r"(a[0]),"r"(a[1]),"r"(a[2]),"r"(a[3]), "r"(b[0]),"r"(b[1]));
}

// =====================================================================
// tf32 mma.sync GEMM: C[m,n] (+epi) = sum_k A[m,k]*B[n,k]
// CTA: 128 x BN, BK=32, 4-stage cp.async. Warps 2(M) x 4(N), warp tile 64 x BN/4.
// epi: 0 plain, 1 cvt-tf32, 2 +residual Rb, 3 scores (*SCALE + bias + mask)
// =====================================================================
#define NSTAGE 4

template<int BN>
__global__ __launch_bounds__(256, 1) void mm_tf32(
    const float* __restrict__ A, const float* __restrict__ B, float* __restrict__ C,
    const float* __restrict__ Rb, const float* __restrict__ Mk,
    int K, int lda, int ldb, int ldc,
    long sAb, long sAh, long sBb, long sBh, long sCb, long sCh,
    int epi)
{
    constexpr int WN = BN / 4;        // warp n-tile (64 or 32)
    constexpr int NF = WN / 8;        // n fragments (8 or 4)
    constexpr int STAGE = (128 + BN) * 32 * 4;
    constexpr int BI = BN / 32;       // B cp.async iters

    extern __shared__ char smem[];
    const uint32_t sbase = (smem_u32(smem) + 127u) & ~127u;

    const int tid = threadIdx.x;
    const int wid = tid >> 5, lane = tid & 31;
    const int wm = (wid >> 2) * 64;
    const int wn = (wid & 3) * WN;
    const int z = blockIdx.z, zb = z >> 4, zh = z & 15;
    const int bm = blockIdx.y * 128, bn = blockIdx.x * BN;

    const float* Ab = A + (size_t)zb * sAb + (size_t)zh * sAh;
    const float* Bb = B + (size_t)zb * sBb + (size_t)zh * sBh;
    float*       Cb = C + (size_t)zb * sCb + (size_t)zh * sCh;

    // per-thread ldmatrix geometry
    const int tA = lane >> 3;
    const int rA = (tA & 1) * 8 + (lane & 7);   // row within m16
    const int cA = tA >> 1;                     // 16B col 0/1
    const int rB = (tA >> 1) * 8 + (lane & 7);  // row within n16
    const int cB = tA & 1;

    float acc[4][NF][4];
    #pragma unroll
    for (int i = 0; i < 4; i++)
        #pragma unroll
        for (int j = 0; j < NF; j++)
            { acc[i][j][0]=0.f; acc[i][j][1]=0.f; acc[i][j][2]=0.f; acc[i][j][3]=0.f; }

    const int nch = K >> 5;

    auto produce = [&](int c) {
        const uint32_t sA = sbase + (c & (NSTAGE-1)) * STAGE;
        const uint32_t sB = sA + 128 * 32 * 4;
        const int k0 = c << 5;
        #pragma unroll
        for (int i = 0; i < 4; i++) {
            int idx = tid + 256 * i; int row = idx >> 3, seg = idx & 7;
            CP16(sA + swz(row * 128 + seg * 16),
                 Ab + (size_t)(bm + row) * lda + k0 + seg * 4);
        }
        #pragma unroll
        for (int i = 0; i < BI; i++) {
            int idx = tid + 256 * i; int row = idx >> 3, seg = idx & 7;
            CP16(sB + swz(row * 128 + seg * 16),
                 Bb + (size_t)(bn + row) * ldb + k0 + seg * 4);
        }
        asm volatile("cp.async.commit_group;" ::: "memory");
    };

    const int pre = nch < 3 ? nch : 3;
    for (int i = 0; i < pre; i++) produce(i);

    for (int c = 0; c < nch; c++) {
        if (c < nch - 2)      asm volatile("cp.async.wait_group 2;" ::: "memory");
        else if (c == nch - 2) asm volatile("cp.async.wait_group 1;" ::: "memory");
        else                   asm volatile("cp.async.wait_group 0;" ::: "memory");
        __syncthreads();
        if (c + 3 < nch) produce(c + 3);

        const uint32_t sA = sbase + (c & (NSTAGE-1)) * STAGE;
        const uint32_t sB = sA + 128 * 32 * 4;
        #pragma unroll
        for (int kk = 0; kk < 4; kk++) {
            uint32_t a[4][4];
            #pragma unroll
            for (int mf = 0; mf < 4; mf++) {
                const int row = wm + mf * 16 + rA;
                ldsm4(a[mf], sA + row * 128 + (((cA + 2*kk) ^ (rA & 7)) * 16));
            }
            uint32_t b[NF][2];
            #pragma unroll
            for (int nf2 = 0; nf2 < NF/2; nf2++) {
                uint32_t t[4];
                const int row = wn + nf2 * 16 + rB;
                ldsm4(t, sB + row * 128 + (((cB + 2*kk) ^ (rB & 7)) * 16));
                b[2*nf2][0]=t[0]; b[2*nf2][1]=t[1];
                b[2*nf2+1][0]=t[2]; b[2*nf2+1][1]=t[3];
            }
            #pragma unroll
            for (int mf = 0; mf < 4; mf++)
                #pragma unroll
                for (int nf = 0; nf < NF; nf++)
                    mma1688(acc[mf][nf], a[mf], b[nf]);
        }
    }
    __syncthreads();

    // ---- epilogue: direct stores, 2 rows x NF*2 cols per (mf) per thread ----
    #pragma unroll
    for (int mf = 0; mf < 4; mf++) {
        const int r0 = bm + wm + mf * 16 + (lane >> 2);
        const int r1 = r0 + 8;
        #pragma unroll
        for (int nf = 0; nf < NF; nf++) {
            const int col = bn + wn + nf * 8 + (lane & 3) * 2;
            float2 v0 = make_float2(acc[mf][nf][0], acc[mf][nf][1]);
            float2 v1 = make_float2(acc[mf][nf][2], acc[mf][nf][3]);
            if (epi == 1) {
                v0.x = to_tf32(v0.x); v0.y = to_tf32(v0.y);
                v1.x = to_tf32(v1.x); v1.y = to_tf32(v1.y);
            } else if (epi == 2) {
                float2 a0 = *(const float2*)(Rb + (size_t)r0 * ldc + col);
                float2 a1 = *(const float2*)(Rb + (size_t)r1 * ldc + col);
                v0.x += a0.x; v0.y += a0.y;
                v1.x += a1.x; v1.y += a1.y;
            } else if (epi == 3) {
                float2 b0 = *(const float2*)(Rb + ((size_t)zh * S_ + r0) * S_ + col);
                float2 b1 = *(const float2*)(Rb + ((size_t)zh * S_ + r1) * S_ + col);
                float2 m0 = *(const float2*)(Mk + (size_t)r0 * S_ + col);
                float2 m1 = *(const float2*)(Mk + (size_t)r1 * S_ + col);
                v0.x = v0.x * SCALE_ + b0.x + m0.x;
                v0.y = v0.y * SCALE_ + b0.y + m0.y;
                v1.x = v1.x * SCALE_ + b1.x + m1.x;
                v1.y = v1.y * SCALE_ + b1.y + m1.y;
            }
            *(float2*)(Cb + (size_t)r0 * ldc + col) = v0;
            *(float2*)(Cb + (size_t)r1 * ldc + col) = v1;
        }
    }
}

// ---------------- weight copy with tf32 rounding ----------------
__global__ __launch_bounds__(256) void cvt_copy(const float* __restrict__ src,
                                                float* __restrict__ dst, size_t n4)
{
    const size_t stride = (size_t)gridDim.x * 256;
    for (size_t i = (size_t)blockIdx.x * 256 + threadIdx.x; i < n4; i += stride) {
        float4 v = *(const float4*)(src + i * 4);
        v.x = to_tf32(v.x); v.y = to_tf32(v.y); v.z = to_tf32(v.z); v.w = to_tf32(v.w);
        *(float4*)(dst + i * 4) = v;
    }
}

// ---------------- rmsnorm (output tf32-rounded) ----------------
__global__ __launch_bounds__(256) void rmsnorm_k(const float* __restrict__ x,
                                                 const float* __restrict__ w,
                                                 float* __restrict__ o)
{
    __shared__ float red[8];
    const size_t row = blockIdx.x;
    const float* xr = x + row * (size_t)DIM_;
    const int tid = threadIdx.x;
    float4 v0 = *(const float4*)(xr + tid*4);
    float4 v1 = *(const float4*)(xr + 1024 + tid*4);
    float s = v0.x*v0.x + v0.y*v0.y + v0.z*v0.z + v0.w*v0.w
            + v1.x*v1.x + v1.y*v1.y + v1.z*v1.z + v1.w*v1.w;
    #pragma unroll
    for (int off = 16; off > 0; off >>= 1) s += __shfl_xor_sync(0xffffffffu, s, off);
    if ((tid & 31) == 0) red[tid >> 5] = s;
    __syncthreads();
    s = red[0]+red[1]+red[2]+red[3]+red[4]+red[5]+red[6]+red[7];
    const float r = rsqrtf(s * (1.0f/DIM_) + EPS_);
    float4 w0 = *(const float4*)(w + tid*4);
    float4 w1 = *(const float4*)(w + 1024 + tid*4);
    float* orow = o + row * (size_t)DIM_;
    float4 o0 = make_float4(to_tf32(v0.x*r*w0.x), to_tf32(v0.y*r*w0.y), to_tf32(v0.z*r*w0.z), to_tf32(v0.w*r*w0.w));
    float4 o1 = make_float4(to_tf32(v1.x*r*w1.x), to_tf32(v1.y*r*w1.y), to_tf32(v1.z*r*w1.z), to_tf32(v1.w*r*w1.w));
    *(float4*)(orow + tid*4) = o0;
    *(float4*)(orow + 1024 + tid*4) = o1;
}

// ---------------- softmax (probs tf32-rounded) ----------------
__global__ __launch_bounds__(256) void softmax_k()
{
    __shared__ float red[8];
    const size_t row = blockIdx.x;
    float* p = g_scores + row * (size_t)S_;
    const int tid = threadIdx.x;
    float4 v0 = *(const float4*)(p + tid*4);
    float4 v1 = *(const float4*)(p + 1024 + tid*4);
    float m = fmaxf(fmaxf(fmaxf(v0.x, v0.y), fmaxf(v0.z, v0.w)),
                    fmaxf(fmaxf(v1.x, v1.y), fmaxf(v1.z, v1.w)));
    #pragma unroll
    for (int off = 16; off > 0; off >>= 1) m = fmaxf(m, __shfl_xor_sync(0xffffffffu, m, off));
    if ((tid & 31) == 0) red[tid >> 5] = m;
    __syncthreads();
    m = fmaxf(fmaxf(fmaxf(red[0], red[1]), fmaxf(red[2], red[3])),
              fmaxf(fmaxf(red[4], red[5]), fmaxf(red[6], red[7])));
    __syncthreads();
    v0.x = __expf(v0.x - m); v0.y = __expf(v0.y - m);
    v0.z = __expf(v0.z - m); v0.w = __expf(v0.w - m);
    v1.x = __expf(v1.x - m); v1.y = __expf(v1.y - m);
    v1.z = __expf(v1.z - m); v1.w = __expf(v1.w - m);
    float s = v0.x+v0.y+v0.z+v0.w + v1.x+v1.y+v1.z+v1.w;
    #pragma unroll
    for (int off = 16; off > 0; off >>= 1) s += __shfl_xor_sync(0xffffffffu, s, off);
    if ((tid & 31) == 0) red[tid >> 5] = s;
    __syncthreads();
    s = red[0]+red[1]+red[2]+red[3]+red[4]+red[5]+red[6]+red[7];
    const float inv = 1.0f / s;
    v0.x = to_tf32(v0.x*inv); v0.y = to_tf32(v0.y*inv);
    v0.z = to_tf32(v0.z*inv); v0.w = to_tf32(v0.w*inv);
    v1.x = to_tf32(v1.x*inv); v1.y = to_tf32(v1.y*inv);
    v1.z = to_tf32(v1.z*inv); v1.w = to_tf32(v1.w*inv);
    *(float4*)(p + tid*4) = v0;
    *(float4*)(p + 1024 + tid*4) = v1;
}

// ---------------- V transpose: g_qkv v-part -> g_vt [b][h*128+d][s] ----------------
__global__ __launch_bounds__(256) void transpose_v()
{
    __shared__ float t[32][33];
    const int b  = blockIdx.z;
    const int s0 = blockIdx.x * 32, j0 = blockIdx.y * 32;
    const int x = threadIdx.x & 31, y = threadIdx.x >> 5;    // 32x8
    #pragma unroll
    for (int yy = y; yy < 32; yy += 8)
        t[yy][x] = g_qkv[(size_t)(b*S_ + s0 + yy) * (3*DIM_) + 2*DIM_ + j0 + x];
    __syncthreads();
    #pragma unroll
    for (int yy = y; yy < 32; yy += 8)
        g_vt[(size_t)(b*DIM_ + j0 + yy) * S_ + s0 + x] = t[x][yy];
}

// ---------------- swiglu: ff = cvt(silu(t1) * t3) ----------------
__global__ __launch_bounds__(256) void swiglu_k()
{
    const size_t i = (size_t)blockIdx.x * 256 + threadIdx.x;   // over M_*HID_/4
    const size_t m = i / (HID_/4), j = (i % (HID_/4)) * 4;
    float4 a = *(const float4*)(g_t13 + m * (2*HID_) + j);
    float4 c = *(const float4*)(g_t13 + m * (2*HID_) + HID_ + j);
    a.x = to_tf32(a.x / (1.0f + __expf(-a.x)) * c.x);
    a.y = to_tf32(a.y / (1.0f + __expf(-a.y)) * c.y);
    a.z = to_tf32(a.z / (1.0f + __expf(-a.z)) * c.z);
    a.w = to_tf32(a.w / (1.0f + __expf(-a.w)) * c.w);
    *(float4*)(g_ff + m * HID_ + j) = a;
}

// ---------------- launch ----------------
extern "C" void kernel_launch(void* const* d_in, const int* in_sizes, int n_in,
                              void* d_out, int out_size)
{
    (void)in_sizes; (void)n_in; (void)out_size;
    const float* x    = (const float*)d_in[0];
    const float* mask = (const float*)d_in[1];
    const float* bias = (const float*)d_in[2];
    const float* wq   = (const float*)d_in[3];
    const float* wk   = (const float*)d_in[4];
    const float* wv   = (const float*)d_in[5];
    const float* wo   = (const float*)d_in[6];
    const float* w1   = (const float*)d_in[7];
    const float* w2   = (const float*)d_in[8];
    const float* w3   = (const float*)d_in[9];
    const float* anw  = (const float*)d_in[10];
    const float* fnw  = (const float*)d_in[11];
    float* out = (float*)d_out;

    float *h, *qkv, *vt, *att, *h1, *f, *t13, *ff, *sc;
    float *cwqkv, *cwo, *cw13, *cw2;
    cudaGetSymbolAddress((void**)&h,    g_h);
    cudaGetSymbolAddress((void**)&qkv,  g_qkv);
    cudaGetSymbolAddress((void**)&vt,   g_vt);
    cudaGetSymbolAddress((void**)&att,  g_att);
    cudaGetSymbolAddress((void**)&h1,   g_h1);
    cudaGetSymbolAddress((void**)&f,    g_f);
    cudaGetSymbolAddress((void**)&t13,  g_t13);
    cudaGetSymbolAddress((void**)&ff,   g_ff);
    cudaGetSymbolAddress((void**)&sc,   g_scores);
    cudaGetSymbolAddress((void**)&cwqkv,g_wqkv);
    cudaGetSymbolAddress((void**)&cwo,  g_wo);
    cudaGetSymbolAddress((void**)&cw13, g_w13);
    cudaGetSymbolAddress((void**)&cw2,  g_w2);

    const int SM256 = NSTAGE * (128 + 256) * 32 * 4 + 256;   // ~196.8KB
    const int SM128 = NSTAGE * (128 + 128) * 32 * 4 + 256;   // ~131.3KB
    cudaFuncSetAttribute(mm_tf32<256>, cudaFuncAttributeMaxDynamicSharedMemorySize, SM256);
    cudaFuncSetAttribute(mm_tf32<128>, cudaFuncAttributeMaxDynamicSharedMemorySize, SM128);

    // weight copies, tf32-rounded (also concatenates qkv and w1/w3)
    cvt_copy<<<1024, 256>>>(wq, cwqkv,                         (size_t)DIM_*DIM_/4);
    cvt_copy<<<1024, 256>>>(wk, cwqkv + (size_t)DIM_*DIM_,     (size_t)DIM_*DIM_/4);
    cvt_copy<<<1024, 256>>>(wv, cwqkv + (size_t)2*DIM_*DIM_,   (size_t)DIM_*DIM_/4);
    cvt_copy<<<1024, 256>>>(wo, cwo,                           (size_t)DIM_*DIM_/4);
    cvt_copy<<<1024, 256>>>(w1, cw13,                          (size_t)HID_*DIM_/4);
    cvt_copy<<<1024, 256>>>(w3, cw13 + (size_t)HID_*DIM_,      (size_t)HID_*DIM_/4);
    cvt_copy<<<1024, 256>>>(w2, cw2,                           (size_t)DIM_*HID_/4);

    // --- attention ---
    rmsnorm_k<<<M_, 256>>>(x, anw, h);
    // qkv: [M,6144] = h[M,2048] @ wqkv^T, cvt epilogue
    mm_tf32<256><<<dim3(3*DIM_/256, M_/128, 1), 256, SM256>>>(
        h, cwqkv, qkv, nullptr, nullptr, DIM_, DIM_, DIM_, 3*DIM_,
        0,0, 0,0, 0,0, 1);
    transpose_v<<<dim3(S_/32, DIM_/32, B_), 256>>>();
    // scores: per (b,h): q @ k^T * scale + bias + mask
    mm_tf32<256><<<dim3(S_/256, S_/128, B_*NH_), 256, SM256>>>(
        qkv, qkv + DIM_, sc, bias, mask, HD_, 3*DIM_, 3*DIM_, S_,
        (long)S_*3*DIM_, HD_, (long)S_*3*DIM_, HD_, 16L*S_*S_, (long)S_*S_, 3);
    softmax_k<<<B_*NH_*S_, 256>>>();
    // pv: per (b,h): probs @ vt^T -> att, cvt epilogue
    mm_tf32<128><<<dim3(1, S_/128, B_*NH_), 256, SM128>>>(
        sc, vt, att, nullptr, nullptr, S_, S_, S_, DIM_,
        16L*S_*S_, (long)S_*S_, (long)DIM_*S_, (long)HD_*S_, (long)S_*DIM_, HD_, 1);
    // wo + residual x
    mm_tf32<256><<<dim3(DIM_/256, M_/128, 1), 256, SM256>>>(
        att, cwo, h1, x, nullptr, DIM_, DIM_, DIM_, DIM_,
        0,0, 0,0, 0,0, 2);

    // --- FFN ---
    rmsnorm_k<<<M_, 256>>>(h1, fnw, f);
    mm_tf32<256><<<dim3(2*HID_/256, M_/128, 1), 256, SM256>>>(
        f, cw13, t13, nullptr, nullptr, DIM_, DIM_, DIM_, 2*HID_,
        0,0, 0,0, 0,0, 0);
    swiglu_k<<<(unsigned)((size_t)M_*HID_/4/256), 256>>>();
    mm_tf32<256><<<dim3(DIM_/256, M_/128, 1), 256, SM256>>>(
        ff, cw2, out, h1, nullptr, HID_, HID_, HID_, DIM_,
        0,0, 0,0, 0,0, 2);
}

// round 4
// speedup vs baseline: 4.1251x; 1.0625x over previous
#include <cuda_runtime.h>
#include <cuda_bf16.h>
#include <math.h>
#include <stdint.h>

// ---------------- problem constants ----------------
#define B_    2
#define S_    2048
#define DIM_  2048
#define NH_   16
#define HD_   128
#define HID_  5632
#define M_    (B_*S_)          // 4096 rows
#define EPS_  1e-5f
#define SCALE_ 0.08838834764831845f   // 1/sqrt(128)

// ---------------- scratch (device globals; no allocation) ----------------
__device__ float g_h   [(size_t)M_*DIM_];
__device__ float g_qkv [(size_t)M_*3*DIM_];          // [m][q|k|v]
__device__ float g_vt  [(size_t)B_*NH_*HD_*S_];      // [b][h][d][s]
__device__ float g_att [(size_t)M_*DIM_];
__device__ float g_h1  [(size_t)M_*DIM_];
__device__ float g_f   [(size_t)M_*DIM_];
__device__ float g_ff  [(size_t)M_*HID_];
// tf32-rounded weight copies
__device__ float g_wqkv[(size_t)3*DIM_*DIM_];
__device__ float g_wo  [(size_t)DIM_*DIM_];
__device__ float g_w13 [(size_t)2*HID_*DIM_];        // interleaved: row 2j=w1[j], 2j+1=w3[j]
__device__ float g_w2  [(size_t)DIM_*HID_];

// ---------------- helpers ----------------
__device__ __forceinline__ uint32_t smem_u32(const void* p){
    uint32_t a;
    asm("{ .reg .u64 t; cvta.to.shared.u64 t, %1; cvt.u32.u64 %0, t; }" : "=r"(a) : "l"(p));
    return a;
}
__device__ __forceinline__ float to_tf32(float x){
    uint32_t u; asm("cvt.rna.tf32.f32 %0, %1;" : "=r"(u) : "f"(x));
    return __uint_as_float(u);
}
__device__ __forceinline__ uint32_t swz(uint32_t x){ return x ^ ((x >> 3) & 0x70); }
#define CP16(dst, src) asm volatile("cp.async.cg.shared.global [%0], [%1], 16;" :: "r"(dst), "l"(src))

__device__ __forceinline__ void ldsm4(uint32_t* r, uint32_t addr){
    asm volatile("ldmatrix.sync.aligned.m8n8.x4.shared.b16 {%0,%1,%2,%3}, [%4];"
        : "=r"(r[0]),"=r"(r[1]),"=r"(r[2]),"=r"(r[3]) : "r"(addr));
}
__device__ __forceinline__ void mma1688(float* c, const uint32_t* a, const uint32_t* b){
    asm volatile("mma.sync.aligned.m16n8k8.row.col.f32.tf32.tf32.f32 "
        "{%0,%1,%2,%3}, {%4,%5,%6,%7}, {%8,%9}, {%0,%1,%2,%3};"
        : "+f"(c[0]),"+f"(c[1]),"+f"(c[2]),"+f"(c[3])
        : "r"(a[0]),"r"(a[1]),"r"(a[2]),"r"(a[3]), "r"(b[0]),"r"(b[1]));
}

// =====================================================================
// tf32 mma.sync GEMM: C[m,n] (+epi) = sum_k A[m,k]*B[n,k]
// epi: 0 plain, 1 cvt-tf32, 2 +residual Rb, 4 swiglu-interleaved (write N/2 cols)
// =====================================================================
#define NSTAGE 4

template<int BN>
__global__ __launch_bounds__(256, 1) void mm_tf32(
    const float* __restrict__ A, const float* __restrict__ B, float* __restrict__ C,
    const float* __restrict__ Rb,
    int K, int lda, int ldb, int ldc, int epi)
{
    constexpr int WN = BN / 4;
    constexpr int NF = WN / 8;
    constexpr int STAGE = (128 + BN) * 32 * 4;
    constexpr int BI = BN / 32;

    extern __shared__ char smem[];
    const uint32_t sbase = (smem_u32(smem) + 127u) & ~127u;

    const int tid = threadIdx.x;
    const int wid = tid >> 5, lane = tid & 31;
    const int wm = (wid >> 2) * 64;
    const int wn = (wid & 3) * WN;
    const int bm = blockIdx.y * 128, bn = blockIdx.x * BN;

    const int tA = lane >> 3;
    const int rA = (tA & 1) * 8 + (lane & 7);
    const int cA = tA >> 1;
    const int rB = (tA >> 1) * 8 + (lane & 7);
    const int cB = tA & 1;

    float acc[4][NF][4];
    #pragma unroll
    for (int i = 0; i < 4; i++)
        #pragma unroll
        for (int j = 0; j < NF; j++)
            { acc[i][j][0]=0.f; acc[i][j][1]=0.f; acc[i][j][2]=0.f; acc[i][j][3]=0.f; }

    const int nch = K >> 5;

    auto produce = [&](int c) {
        const uint32_t sA = sbase + (c & (NSTAGE-1)) * STAGE;
        const uint32_t sB = sA + 128 * 32 * 4;
        const int k0 = c << 5;
        #pragma unroll
        for (int i = 0; i < 4; i++) {
            int idx = tid + 256 * i; int row = idx >> 3, seg = idx & 7;
            CP16(sA + swz(row * 128 + seg * 16),
                 A + (size_t)(bm + row) * lda + k0 + seg * 4);
        }
        #pragma unroll
        for (int i = 0; i < BI; i++) {
            int idx = tid + 256 * i; int row = idx >> 3, seg = idx & 7;
            CP16(sB + swz(row * 128 + seg * 16),
                 B + (size_t)(bn + row) * ldb + k0 + seg * 4);
        }
        asm volatile("cp.async.commit_group;" ::: "memory");
    };

    const int pre = nch < 3 ? nch : 3;
    for (int i = 0; i < pre; i++) produce(i);

    for (int c = 0; c < nch; c++) {
        if (c < nch - 2)       asm volatile("cp.async.wait_group 2;" ::: "memory");
        else if (c == nch - 2) asm volatile("cp.async.wait_group 1;" ::: "memory");
        else                   asm volatile("cp.async.wait_group 0;" ::: "memory");
        __syncthreads();
        if (c + 3 < nch) produce(c + 3);

        const uint32_t sA = sbase + (c & (NSTAGE-1)) * STAGE;
        const uint32_t sB = sA + 128 * 32 * 4;
        #pragma unroll
        for (int kk = 0; kk < 4; kk++) {
            uint32_t a[4][4];
            #pragma unroll
            for (int mf = 0; mf < 4; mf++) {
                const int row = wm + mf * 16 + rA;
                ldsm4(a[mf], sA + row * 128 + (((cA + 2*kk) ^ (rA & 7)) * 16));
            }
            uint32_t b[NF][2];
            #pragma unroll
            for (int nf2 = 0; nf2 < NF/2; nf2++) {
                uint32_t t[4];
                const int row = wn + nf2 * 16 + rB;
                ldsm4(t, sB + row * 128 + (((cB + 2*kk) ^ (rB & 7)) * 16));
                b[2*nf2][0]=t[0]; b[2*nf2][1]=t[1];
                b[2*nf2+1][0]=t[2]; b[2*nf2+1][1]=t[3];
            }
            #pragma unroll
            for (int mf = 0; mf < 4; mf++)
                #pragma unroll
                for (int nf = 0; nf < NF; nf++)
                    mma1688(acc[mf][nf], a[mf], b[nf]);
        }
    }
    __syncthreads();

    #pragma unroll
    for (int mf = 0; mf < 4; mf++) {
        const int r0 = bm + wm + mf * 16 + (lane >> 2);
        const int r1 = r0 + 8;
        #pragma unroll
        for (int nf = 0; nf < NF; nf++) {
            const int col = bn + wn + nf * 8 + (lane & 3) * 2;
            float2 v0 = make_float2(acc[mf][nf][0], acc[mf][nf][1]);
            float2 v1 = make_float2(acc[mf][nf][2], acc[mf][nf][3]);
            if (epi == 4) {
                // v = (t1_j, t3_j); out[j] = tf32(silu(t1)*t3), j = col/2
                float a0 = v0.x / (1.0f + __expf(-v0.x)) * v0.y;
                float a1 = v1.x / (1.0f + __expf(-v1.x)) * v1.y;
                C[(size_t)r0 * ldc + (col >> 1)] = to_tf32(a0);
                C[(size_t)r1 * ldc + (col >> 1)] = to_tf32(a1);
                continue;
            }
            if (epi == 1) {
                v0.x = to_tf32(v0.x); v0.y = to_tf32(v0.y);
                v1.x = to_tf32(v1.x); v1.y = to_tf32(v1.y);
            } else if (epi == 2) {
                float2 a0 = *(const float2*)(Rb + (size_t)r0 * ldc + col);
                float2 a1 = *(const float2*)(Rb + (size_t)r1 * ldc + col);
                v0.x += a0.x; v0.y += a0.y;
                v1.x += a1.x; v1.y += a1.y;
            }
            *(float2*)(C + (size_t)r0 * ldc + col) = v0;
            *(float2*)(C + (size_t)r1 * ldc + col) = v1;
        }
    }
}

// =====================================================================
// Flash attention: per CTA = 128 q rows x 1 head, loop 32 kv tiles of 64.
// 8 warps, warp owns 16 q rows. smem: Q(67584, reused as P) K[2](33792) V[2](34816)
// =====================================================================
#define FL_SMEM (204800 + 128)

__global__ __launch_bounds__(256, 1) void flash_k(const float* __restrict__ bias,
                                                  const float* __restrict__ mask)
{
    extern __shared__ char smem[];
    const uint32_t sb = (smem_u32(smem) + 127u) & ~127u;

    const int tid = threadIdx.x;
    const int w = tid >> 5, lane = tid & 31;
    const int tA = lane >> 3;
    const int rA = (tA & 1) * 8 + (lane & 7);
    const int cA = tA >> 1;
    const int rB = (tA >> 1) * 8 + (lane & 7);
    const int cB = tA & 1;

    const int z = blockIdx.y, b = z >> 4, h = z & 15;
    const int bm = blockIdx.x * 128;

    const float* qbase = g_qkv + (size_t)(b*S_ + bm) * (3*DIM_) + h*HD_;
    const float* kbase = g_qkv + (size_t)(b*S_) * (3*DIM_) + DIM_ + h*HD_;
    const float* vbase = g_vt + (size_t)z * HD_ * S_;

    auto loadKV = [&](int kt, int buf) {
        const uint32_t ok = sb + 67584 + buf * 33792;
        const uint32_t ov = sb + 135168 + buf * 34816;
        #pragma unroll
        for (int i = 0; i < 8; i++) {
            int idx = tid + 256*i; int r = idx >> 5, sg = idx & 31;
            CP16(ok + r*528 + sg*16, kbase + (size_t)(kt*64 + r) * (3*DIM_) + sg*4);
        }
        #pragma unroll
        for (int i = 0; i < 8; i++) {
            int idx = tid + 256*i; int r = idx >> 4, sg = idx & 15;
            CP16(ov + r*272 + sg*16, vbase + (size_t)r * S_ + kt*64 + sg*4);
        }
        asm volatile("cp.async.commit_group;" ::: "memory");
    };

    // Q tile -> smem (pitch 528)
    #pragma unroll
    for (int i = 0; i < 16; i++) {
        int idx = tid + 256*i; int r = idx >> 5, sg = idx & 31;
        CP16(sb + r*528 + sg*16, qbase + (size_t)r * (3*DIM_) + sg*4);
    }
    asm volatile("cp.async.commit_group;" ::: "memory");
    loadKV(0, 0);
    loadKV(1, 1);
    asm volatile("cp.async.wait_group 2;" ::: "memory");
    __syncthreads();

    // Q fragments (16 ksteps over d=128)
    uint32_t qf[16][4];
    #pragma unroll
    for (int kb = 0; kb < 16; kb++)
        ldsm4(qf[kb], sb + (w*16 + rA)*528 + (cA + 2*kb)*16);
    __syncthreads();   // all warps done reading Q before P overwrites region

    const int gr0 = bm + w*16 + (lane >> 2);
    const int gr1 = gr0 + 8;

    float m0 = -1e30f, m1 = -1e30f, l0 = 0.f, l1 = 0.f;
    float oacc[16][4];
    #pragma unroll
    for (int i = 0; i < 16; i++)
        { oacc[i][0]=0.f; oacc[i][1]=0.f; oacc[i][2]=0.f; oacc[i][3]=0.f; }

    for (int kt = 0; kt < 32; kt++) {
        if (kt < 31) asm volatile("cp.async.wait_group 1;" ::: "memory");
        else         asm volatile("cp.async.wait_group 0;" ::: "memory");
        __syncthreads();
        const int buf = kt & 1;
        const uint32_t ok = sb + 67584 + buf * 33792;
        const uint32_t ov = sb + 135168 + buf * 34816;

        // ---- S = Q @ K^T (warp: 16 q x 64 kv) ----
        float sacc[8][4];
        #pragma unroll
        for (int i = 0; i < 8; i++)
            { sacc[i][0]=0.f; sacc[i][1]=0.f; sacc[i][2]=0.f; sacc[i][3]=0.f; }
        #pragma unroll
        for (int kb = 0; kb < 16; kb++) {
            #pragma unroll
            for (int nf2 = 0; nf2 < 4; nf2++) {
                uint32_t t[4];
                ldsm4(t, ok + (nf2*16 + rB)*528 + (cB + 2*kb)*16);
                uint32_t b0[2] = {t[0], t[1]}, b1[2] = {t[2], t[3]};
                mma1688(sacc[2*nf2],   qf[kb], b0);
                mma1688(sacc[2*nf2+1], qf[kb], b1);
            }
        }

        // ---- scale + bias + mask, online softmax ----
        float p[8][4];
        float rmax0 = -1e30f, rmax1 = -1e30f;
        #pragma unroll
        for (int nf = 0; nf < 8; nf++) {
            const int gc = kt*64 + nf*8 + (lane & 3)*2;
            float2 bb0 = *(const float2*)(bias + ((size_t)h*S_ + gr0)*S_ + gc);
            float2 mk0 = *(const float2*)(mask + (size_t)gr0*S_ + gc);
            float2 bb1 = *(const float2*)(bias + ((size_t)h*S_ + gr1)*S_ + gc);
            float2 mk1 = *(const float2*)(mask + (size_t)gr1*S_ + gc);
            p[nf][0] = sacc[nf][0]*SCALE_ + (bb0.x + mk0.x);
            p[nf][1] = sacc[nf][1]*SCALE_ + (bb0.y + mk0.y);
            p[nf][2] = sacc[nf][2]*SCALE_ + (bb1.x + mk1.x);
            p[nf][3] = sacc[nf][3]*SCALE_ + (bb1.y + mk1.y);
            rmax0 = fmaxf(rmax0, fmaxf(p[nf][0], p[nf][1]));
            rmax1 = fmaxf(rmax1, fmaxf(p[nf][2], p[nf][3]));
        }
        rmax0 = fmaxf(rmax0, __shfl_xor_sync(0xffffffffu, rmax0, 1));
        rmax0 = fmaxf(rmax0, __shfl_xor_sync(0xffffffffu, rmax0, 2));
        rmax1 = fmaxf(rmax1, __shfl_xor_sync(0xffffffffu, rmax1, 1));
        rmax1 = fmaxf(rmax1, __shfl_xor_sync(0xffffffffu, rmax1, 2));

        const float mn0 = fmaxf(m0, rmax0), mn1 = fmaxf(m1, rmax1);
        const float al0 = __expf(m0 - mn0), al1 = __expf(m1 - mn1);
        m0 = mn0; m1 = mn1;

        float rs0 = 0.f, rs1 = 0.f;
        #pragma unroll
        for (int nf = 0; nf < 8; nf++) {
            p[nf][0] = __expf(p[nf][0] - mn0);
            p[nf][1] = __expf(p[nf][1] - mn0);
            p[nf][2] = __expf(p[nf][2] - mn1);
            p[nf][3] = __expf(p[nf][3] - mn1);
            rs0 += p[nf][0] + p[nf][1];
            rs1 += p[nf][2] + p[nf][3];
        }
        rs0 += __shfl_xor_sync(0xffffffffu, rs0, 1);
        rs0 += __shfl_xor_sync(0xffffffffu, rs0, 2);
        rs1 += __shfl_xor_sync(0xffffffffu, rs1, 1);
        rs1 += __shfl_xor_sync(0xffffffffu, rs1, 2);
        l0 = l0 * al0 + rs0;
        l1 = l1 * al1 + rs1;

        #pragma unroll
        for (int i = 0; i < 16; i++) {
            oacc[i][0] *= al0; oacc[i][1] *= al0;
            oacc[i][2] *= al1; oacc[i][3] *= al1;
        }

        // ---- store P (tf32) into warp-private smem rows, pitch 272 ----
        {
            const uint32_t pr0 = sb + (w*16 + (lane>>2))*272 + ((lane & 3)*2)*4;
            #pragma unroll
            for (int nf = 0; nf < 8; nf++) {
                float2 a0 = make_float2(to_tf32(p[nf][0]), to_tf32(p[nf][1]));
                float2 a1 = make_float2(to_tf32(p[nf][2]), to_tf32(p[nf][3]));
                asm volatile("st.shared.v2.f32 [%0], {%1,%2};" :: "r"(pr0 + nf*32), "f"(a0.x), "f"(a0.y) : "memory");
                asm volatile("st.shared.v2.f32 [%0], {%1,%2};" :: "r"(pr0 + 8*272 + nf*32), "f"(a1.x), "f"(a1.y) : "memory");
            }
        }
        __syncwarp();

        // ---- O += P @ V (warp: 16 q x 128 d, k = 64 kv) ----
        #pragma unroll
        for (int kb = 0; kb < 8; kb++) {
            uint32_t pa[4];
            ldsm4(pa, sb + (w*16 + rA)*272 + (cA + 2*kb)*16);
            #pragma unroll
            for (int nf2 = 0; nf2 < 8; nf2++) {
                uint32_t t[4];
                ldsm4(t, ov + (nf2*16 + rB)*272 + (cB + 2*kb)*16);
                uint32_t b0[2] = {t[0], t[1]}, b1[2] = {t[2], t[3]};
                mma1688(oacc[2*nf2],   pa, b0);
                mma1688(oacc[2*nf2+1], pa, b1);
            }
        }
        __syncthreads();
        if (kt + 2 < 32) loadKV(kt + 2, buf);
    }

    // ---- output: att = tf32(O / l) ----
    const float inv0 = 1.0f / l0, inv1 = 1.0f / l1;
    float* o0 = g_att + (size_t)(b*S_ + gr0) * DIM_ + h*HD_;
    float* o1 = g_att + (size_t)(b*S_ + gr1) * DIM_ + h*HD_;
    #pragma unroll
    for (int nfd = 0; nfd < 16; nfd++) {
        const int dc = nfd*8 + (lane & 3)*2;
        *(float2*)(o0 + dc) = make_float2(to_tf32(oacc[nfd][0]*inv0), to_tf32(oacc[nfd][1]*inv0));
        *(float2*)(o1 + dc) = make_float2(to_tf32(oacc[nfd][2]*inv1), to_tf32(oacc[nfd][3]*inv1));
    }
}

// ---------------- weight copy with tf32 rounding ----------------
__global__ __launch_bounds__(256) void cvt_copy(const float* __restrict__ src,
                                                float* __restrict__ dst, size_t n4)
{
    const size_t stride = (size_t)gridDim.x * 256;
    for (size_t i = (size_t)blockIdx.x * 256 + threadIdx.x; i < n4; i += stride) {
        float4 v = *(const float4*)(src + i * 4);
        v.x = to_tf32(v.x); v.y = to_tf32(v.y); v.z = to_tf32(v.z); v.w = to_tf32(v.w);
        *(float4*)(dst + i * 4) = v;
    }
}

// ---------------- interleave w1/w3 rows (tf32-rounded) ----------------
__global__ __launch_bounds__(256) void ilv_w13(const float* __restrict__ w1,
                                               const float* __restrict__ w3,
                                               float* __restrict__ dst)
{
    const size_t idx = (size_t)blockIdx.x * 256 + threadIdx.x;   // over 2*HID*512
    const size_t rr = idx >> 9, sg = idx & 511;
    const float* src = (rr & 1) ? w3 : w1;
    float4 v = *(const float4*)(src + (rr >> 1) * DIM_ + sg * 4);
    v.x = to_tf32(v.x); v.y = to_tf32(v.y); v.z = to_tf32(v.z); v.w = to_tf32(v.w);
    *(float4*)(dst + rr * DIM_ + sg * 4) = v;
}

// ---------------- rmsnorm (output tf32-rounded) ----------------
__global__ __launch_bounds__(256) void rmsnorm_k(const float* __restrict__ x,
                                                 const float* __restrict__ w,
                                                 float* __restrict__ o)
{
    __shared__ float red[8];
    const size_t row = blockIdx.x;
    const float* xr = x + row * (size_t)DIM_;
    const int tid = threadIdx.x;
    float4 v0 = *(const float4*)(xr + tid*4);
    float4 v1 = *(const float4*)(xr + 1024 + tid*4);
    float s = v0.x*v0.x + v0.y*v0.y + v0.z*v0.z + v0.w*v0.w
            + v1.x*v1.x + v1.y*v1.y + v1.z*v1.z + v1.w*v1.w;
    #pragma unroll
    for (int off = 16; off > 0; off >>= 1) s += __shfl_xor_sync(0xffffffffu, s, off);
    if ((tid & 31) == 0) red[tid >> 5] = s;
    __syncthreads();
    s = red[0]+red[1]+red[2]+red[3]+red[4]+red[5]+red[6]+red[7];
    const float r = rsqrtf(s * (1.0f/DIM_) + EPS_);
    float4 w0 = *(const float4*)(w + tid*4);
    float4 w1 = *(const float4*)(w + 1024 + tid*4);
    float* orow = o + row * (size_t)DIM_;
    float4 o0 = make_float4(to_tf32(v0.x*r*w0.x), to_tf32(v0.y*r*w0.y), to_tf32(v0.z*r*w0.z), to_tf32(v0.w*r*w0.w));
    float4 o1 = make_float4(to_tf32(v1.x*r*w1.x), to_tf32(v1.y*r*w1.y), to_tf32(v1.z*r*w1.z), to_tf32(v1.w*r*w1.w));
    *(float4*)(orow + tid*4) = o0;
    *(float4*)(orow + 1024 + tid*4) = o1;
}

// ---------------- V transpose: g_qkv v-part -> g_vt [b][h*128+d][s] ----------------
__global__ __launch_bounds__(256) void transpose_v()
{
    __shared__ float t[32][33];
    const int b  = blockIdx.z;
    const int s0 = blockIdx.x * 32, j0 = blockIdx.y * 32;
    const int x = threadIdx.x & 31, y = threadIdx.x >> 5;
    #pragma unroll
    for (int yy = y; yy < 32; yy += 8)
        t[yy][x] = g_qkv[(size_t)(b*S_ + s0 + yy) * (3*DIM_) + 2*DIM_ + j0 + x];
    __syncthreads();
    #pragma unroll
    for (int yy = y; yy < 32; yy += 8)
        g_vt[(size_t)(b*DIM_ + j0 + yy) * S_ + s0 + x] = t[x][yy];
}

// ---------------- launch ----------------
extern "C" void kernel_launch(void* const* d_in, const int* in_sizes, int n_in,
                              void* d_out, int out_size)
{
    (void)in_sizes; (void)n_in; (void)out_size;
    const float* x    = (const float*)d_in[0];
    const float* mask = (const float*)d_in[1];
    const float* bias = (const float*)d_in[2];
    const float* wq   = (const float*)d_in[3];
    const float* wk   = (const float*)d_in[4];
    const float* wv   = (const float*)d_in[5];
    const float* wo   = (const float*)d_in[6];
    const float* w1   = (const float*)d_in[7];
    const float* w2   = (const float*)d_in[8];
    const float* w3   = (const float*)d_in[9];
    const float* anw  = (const float*)d_in[10];
    const float* fnw  = (const float*)d_in[11];
    float* out = (float*)d_out;

    float *h, *qkv, *att, *h1, *f, *ff;
    float *cwqkv, *cwo, *cw13, *cw2;
    cudaGetSymbolAddress((void**)&h,    g_h);
    cudaGetSymbolAddress((void**)&qkv,  g_qkv);
    cudaGetSymbolAddress((void**)&att,  g_att);
    cudaGetSymbolAddress((void**)&h1,   g_h1);
    cudaGetSymbolAddress((void**)&f,    g_f);
    cudaGetSymbolAddress((void**)&ff,   g_ff);
    cudaGetSymbolAddress((void**)&cwqkv,g_wqkv);
    cudaGetSymbolAddress((void**)&cwo,  g_wo);
    cudaGetSymbolAddress((void**)&cw13, g_w13);
    cudaGetSymbolAddress((void**)&cw2,  g_w2);

    const int SM256 = NSTAGE * (128 + 256) * 32 * 4 + 256;
    cudaFuncSetAttribute(mm_tf32<256>, cudaFuncAttributeMaxDynamicSharedMemorySize, SM256);
    cudaFuncSetAttribute(flash_k, cudaFuncAttributeMaxDynamicSharedMemorySize, FL_SMEM);

    // weight prep (tf32-rounded; qkv concat, w1/w3 interleave)
    cvt_copy<<<1024, 256>>>(wq, cwqkv,                       (size_t)DIM_*DIM_/4);
    cvt_copy<<<1024, 256>>>(wk, cwqkv + (size_t)DIM_*DIM_,   (size_t)DIM_*DIM_/4);
    cvt_copy<<<1024, 256>>>(wv, cwqkv + (size_t)2*DIM_*DIM_, (size_t)DIM_*DIM_/4);
    cvt_copy<<<1024, 256>>>(wo, cwo,                         (size_t)DIM_*DIM_/4);
    ilv_w13<<<(unsigned)((size_t)2*HID_*512/256), 256>>>(w1, w3, cw13);
    cvt_copy<<<1024, 256>>>(w2, cw2,                         (size_t)DIM_*HID_/4);

    // --- attention ---
    rmsnorm_k<<<M_, 256>>>(x, anw, h);
    mm_tf32<256><<<dim3(3*DIM_/256, M_/128), 256, SM256>>>(
        h, cwqkv, qkv, nullptr, DIM_, DIM_, DIM_, 3*DIM_, 1);
    transpose_v<<<dim3(S_/32, DIM_/32, B_), 256>>>();
    flash_k<<<dim3(S_/128, B_*NH_), 256, FL_SMEM>>>(bias, mask);
    mm_tf32<256><<<dim3(DIM_/256, M_/128), 256, SM256>>>(
        att, cwo, h1, x, DIM_, DIM_, DIM_, DIM_, 2);

    // --- FFN ---
    rmsnorm_k<<<M_, 256>>>(h1, fnw, f);
    mm_tf32<256><<<dim3(2*HID_/256, M_/128), 256, SM256>>>(
        f, cw13, ff, nullptr, DIM_, DIM_, DIM_, HID_, 4);
    mm_tf32<256><<<dim3(DIM_/256, M_/128), 256, SM256>>>(
        ff, cw2, out, h1, HID_, HID_, HID_, DIM_, 2);
}

// round 6
// speedup vs baseline: 6.7023x; 1.6248x over previous
#include <cuda_runtime.h>
#include <cuda_fp16.h>
#include <math.h>
#include <stdint.h>

// ---------------- problem constants ----------------
#define B_    2
#define S_    2048
#define DIM_  2048
#define NH_   16
#define HD_   128
#define HID_  5632
#define M_    (B_*S_)
#define EPS_  1e-5f
#define SCALE_ 0.08838834764831845f   // 1/sqrt(128)

// ---------------- scratch (device globals; no allocation) ----------------
__device__ __half g_h   [(size_t)M_*DIM_];
__device__ __half g_qkv [(size_t)M_*3*DIM_];          // [m][q|k|v]
__device__ __half g_vt  [(size_t)B_*NH_*HD_*S_];      // [b][h][d][s]
__device__ __half g_att [(size_t)M_*DIM_];
__device__ float  g_h1  [(size_t)M_*DIM_];
__device__ __half g_f   [(size_t)M_*DIM_];
__device__ __half g_ff  [(size_t)M_*HID_];
// fp16 weight copies
__device__ __half g_wqkv[(size_t)3*DIM_*DIM_];
__device__ __half g_wo  [(size_t)DIM_*DIM_];
__device__ __half g_w13 [(size_t)2*HID_*DIM_];        // interleaved rows: 2j=w1[j], 2j+1=w3[j]
__device__ __half g_w2  [(size_t)DIM_*HID_];

// ---------------- helpers ----------------
__device__ __forceinline__ uint32_t smem_u32(const void* p){
    uint32_t a;
    asm("{ .reg .u64 t; cvta.to.shared.u64 t, %1; cvt.u32.u64 %0, t; }" : "=r"(a) : "l"(p));
    return a;
}
__device__ __forceinline__ uint32_t swz(uint32_t x){ return x ^ ((x >> 3) & 0x70); }
#define CP16(dst, src) asm volatile("cp.async.cg.shared.global [%0], [%1], 16;" :: "r"(dst), "l"(src))

__device__ __forceinline__ void ldsm4(uint32_t* r, uint32_t addr){
    asm volatile("ldmatrix.sync.aligned.m8n8.x4.shared.b16 {%0,%1,%2,%3}, [%4];"
        : "=r"(r[0]),"=r"(r[1]),"=r"(r[2]),"=r"(r[3]) : "r"(addr));
}
__device__ __forceinline__ void mma16816(float* c, const uint32_t* a, const uint32_t* b){
    asm volatile("mma.sync.aligned.m16n8k16.row.col.f32.f16.f16.f32 "
        "{%0,%1,%2,%3}, {%4,%5,%6,%7}, {%8,%9}, {%0,%1,%2,%3};"
        : "+f"(c[0]),"+f"(c[1]),"+f"(c[2]),"+f"(c[3])
        : "r"(a[0]),"r"(a[1]),"r"(a[2]),"r"(a[3]), "r"(b[0]),"r"(b[1]));
}
__device__ __forceinline__ uint32_t pack2h(float a, float b){
    __half2 h = __floats2half2_rn(a, b);
    return *reinterpret_cast<uint32_t*>(&h);
}

// =====================================================================
// fp16 mma.sync GEMM: C[m,n] (+epi) = sum_k A[m,k]*B[n,k]
// CTA 128 x BN, BK=64 (128B rows, SW128), 4-stage cp.async.
// epi: 1 half-out, 2 fp32-out + residual Rb, 4 swiglu-interleaved half-out (N/2 cols)
// =====================================================================
#define NSTAGE 4

template<int BN>
__global__ __launch_bounds__(256, 1) void mm_h(
    const __half* __restrict__ A, const __half* __restrict__ B, void* __restrict__ Cv,
    const float* __restrict__ Rb,
    int K, int lda, int ldb, int ldc, int epi)
{
    constexpr int WN = BN / 4;
    constexpr int NF = WN / 8;
    constexpr int STAGE = (128 + BN) * 128;   // bytes per stage (64 halfs/row)
    constexpr int BI = BN / 32;

    extern __shared__ char smem[];
    const uint32_t sbase = (smem_u32(smem) + 127u) & ~127u;

    const int tid = threadIdx.x;
    const int wid = tid >> 5, lane = tid & 31;
    const int wm = (wid >> 2) * 64;
    const int wn = (wid & 3) * WN;
    const int bm = blockIdx.y * 128, bn = blockIdx.x * BN;

    const int tA = lane >> 3;
    const int rA = (tA & 1) * 8 + (lane & 7);
    const int cA = tA >> 1;
    const int rB = (tA >> 1) * 8 + (lane & 7);
    const int cB = tA & 1;

    float acc[4][NF][4];
    #pragma unroll
    for (int i = 0; i < 4; i++)
        #pragma unroll
        for (int j = 0; j < NF; j++)
            { acc[i][j][0]=0.f; acc[i][j][1]=0.f; acc[i][j][2]=0.f; acc[i][j][3]=0.f; }

    const int nch = K >> 6;

    auto produce = [&](int c) {
        const uint32_t sA = sbase + (c & (NSTAGE-1)) * STAGE;
        const uint32_t sB = sA + 128 * 128;
        const int k0 = c << 6;
        #pragma unroll
        for (int i = 0; i < 4; i++) {
            int idx = tid + 256 * i; int row = idx >> 3, seg = idx & 7;
            CP16(sA + swz(row * 128 + seg * 16),
                 A + (size_t)(bm + row) * lda + k0 + seg * 8);
        }
        #pragma unroll
        for (int i = 0; i < BI; i++) {
            int idx = tid + 256 * i; int row = idx >> 3, seg = idx & 7;
            CP16(sB + swz(row * 128 + seg * 16),
                 B + (size_t)(bn + row) * ldb + k0 + seg * 8);
        }
        asm volatile("cp.async.commit_group;" ::: "memory");
    };

    const int pre = nch < 3 ? nch : 3;
    for (int i = 0; i < pre; i++) produce(i);

    for (int c = 0; c < nch; c++) {
        if (c < nch - 2)       asm volatile("cp.async.wait_group 2;" ::: "memory");
        else if (c == nch - 2) asm volatile("cp.async.wait_group 1;" ::: "memory");
        else                   asm volatile("cp.async.wait_group 0;" ::: "memory");
        __syncthreads();
        if (c + 3 < nch) produce(c + 3);

        const uint32_t sA = sbase + (c & (NSTAGE-1)) * STAGE;
        const uint32_t sB = sA + 128 * 128;
        #pragma unroll
        for (int kk = 0; kk < 4; kk++) {           // 4 x k16
            uint32_t a[4][4];
            #pragma unroll
            for (int mf = 0; mf < 4; mf++) {
                const int row = wm + mf * 16 + rA;
                ldsm4(a[mf], sA + row * 128 + (((cA + 2*kk) ^ (rA & 7)) * 16));
            }
            uint32_t b[NF][2];
            #pragma unroll
            for (int nf2 = 0; nf2 < NF/2; nf2++) {
                uint32_t t[4];
                const int row = wn + nf2 * 16 + rB;
                ldsm4(t, sB + row * 128 + (((cB + 2*kk) ^ (rB & 7)) * 16));
                b[2*nf2][0]=t[0]; b[2*nf2][1]=t[1];
                b[2*nf2+1][0]=t[2]; b[2*nf2+1][1]=t[3];
            }
            #pragma unroll
            for (int mf = 0; mf < 4; mf++)
                #pragma unroll
                for (int nf = 0; nf < NF; nf++)
                    mma16816(acc[mf][nf], a[mf], b[nf]);
        }
    }
    __syncthreads();

    #pragma unroll
    for (int mf = 0; mf < 4; mf++) {
        const int r0 = bm + wm + mf * 16 + (lane >> 2);
        const int r1 = r0 + 8;
        #pragma unroll
        for (int nf = 0; nf < NF; nf++) {
            const int col = bn + wn + nf * 8 + (lane & 3) * 2;
            float2 v0 = make_float2(acc[mf][nf][0], acc[mf][nf][1]);
            float2 v1 = make_float2(acc[mf][nf][2], acc[mf][nf][3]);
            if (epi == 4) {
                __half* C = (__half*)Cv;
                float a0 = v0.x / (1.0f + __expf(-v0.x)) * v0.y;
                float a1 = v1.x / (1.0f + __expf(-v1.x)) * v1.y;
                C[(size_t)r0 * ldc + (col >> 1)] = __float2half_rn(a0);
                C[(size_t)r1 * ldc + (col >> 1)] = __float2half_rn(a1);
            } else if (epi == 1) {
                __half* C = (__half*)Cv;
                *(uint32_t*)(C + (size_t)r0 * ldc + col) = pack2h(v0.x, v0.y);
                *(uint32_t*)(C + (size_t)r1 * ldc + col) = pack2h(v1.x, v1.y);
            } else {
                float* C = (float*)Cv;
                float2 a0 = *(const float2*)(Rb + (size_t)r0 * ldc + col);
                float2 a1 = *(const float2*)(Rb + (size_t)r1 * ldc + col);
                v0.x += a0.x; v0.y += a0.y;
                v1.x += a1.x; v1.y += a1.y;
                *(float2*)(C + (size_t)r0 * ldc + col) = v0;
                *(float2*)(C + (size_t)r1 * ldc + col) = v1;
            }
        }
    }
}

// =====================================================================
// Flash attention (fp16 inputs, fp32 softmax/accum)
// CTA = 128 q rows x 1 head, 32 kv tiles of 64. 8 warps, warp = 16 q rows.
// smem: Q/P @0 (pitch 272, 34816) | K x2 (pitch 272, 17408 ea) | V x2 (pitch 144, 18432 ea)
// =====================================================================
#define FL_SMEM (106624)

__global__ __launch_bounds__(256, 2) void flash_k(const float* __restrict__ bias,
                                                  const float* __restrict__ mask)
{
    extern __shared__ char smem[];
    const uint32_t sb = (smem_u32(smem) + 127u) & ~127u;

    const int tid = threadIdx.x;
    const int w = tid >> 5, lane = tid & 31;
    const int tA = lane >> 3;
    const int rA = (tA & 1) * 8 + (lane & 7);
    const int cA = tA >> 1;
    const int rB = (tA >> 1) * 8 + (lane & 7);
    const int cB = tA & 1;

    const int z = blockIdx.y, b = z >> 4, h = z & 15;
    const int bm = blockIdx.x * 128;

    const __half* qbase = g_qkv + (size_t)(b*S_ + bm) * (3*DIM_) + h*HD_;
    const __half* kbase = g_qkv + (size_t)(b*S_) * (3*DIM_) + DIM_ + h*HD_;
    const __half* vbase = g_vt + (size_t)z * HD_ * S_;

    auto loadKV = [&](int kt, int buf) {
        const uint32_t ok = sb + 34816 + buf * 17408;
        const uint32_t ov = sb + 69632 + buf * 18432;
        #pragma unroll
        for (int i = 0; i < 4; i++) {       // K: 64 rows x 16 segs
            int idx = tid + 256*i; int r = idx >> 4, sg = idx & 15;
            CP16(ok + r*272 + sg*16, kbase + (size_t)(kt*64 + r) * (3*DIM_) + sg*8);
        }
        #pragma unroll
        for (int i = 0; i < 4; i++) {       // V: 128 d-rows x 8 segs
            int idx = tid + 256*i; int r = idx >> 3, sg = idx & 7;
            CP16(ov + r*144 + sg*16, vbase + (size_t)r * S_ + kt*64 + sg*8);
        }
        asm volatile("cp.async.commit_group;" ::: "memory");
    };

    // Q tile -> smem (128 rows x 16 segs, pitch 272)
    #pragma unroll
    for (int i = 0; i < 8; i++) {
        int idx = tid + 256*i; int r = idx >> 4, sg = idx & 15;
        CP16(sb + r*272 + sg*16, qbase + (size_t)r * (3*DIM_) + sg*8);
    }
    asm volatile("cp.async.commit_group;" ::: "memory");
    loadKV(0, 0);
    loadKV(1, 1);
    asm volatile("cp.async.wait_group 2;" ::: "memory");
    __syncthreads();

    // Q fragments: 8 ksteps of k16 over d=128
    uint32_t qf[8][4];
    #pragma unroll
    for (int kb = 0; kb < 8; kb++)
        ldsm4(qf[kb], sb + (w*16 + rA)*272 + (cA + 2*kb)*16);
    __syncthreads();

    const int gr0 = bm + w*16 + (lane >> 2);
    const int gr1 = gr0 + 8;

    float m0 = -1e30f, m1 = -1e30f, l0 = 0.f, l1 = 0.f;
    float oacc[16][4];
    #pragma unroll
    for (int i = 0; i < 16; i++)
        { oacc[i][0]=0.f; oacc[i][1]=0.f; oacc[i][2]=0.f; oacc[i][3]=0.f; }

    for (int kt = 0; kt < 32; kt++) {
        if (kt < 31) asm volatile("cp.async.wait_group 1;" ::: "memory");
        else         asm volatile("cp.async.wait_group 0;" ::: "memory");
        __syncthreads();
        const int buf = kt & 1;
        const uint32_t ok = sb + 34816 + buf * 17408;
        const uint32_t ov = sb + 69632 + buf * 18432;

        // ---- S = Q @ K^T ----
        float sacc[8][4];
        #pragma unroll
        for (int i = 0; i < 8; i++)
            { sacc[i][0]=0.f; sacc[i][1]=0.f; sacc[i][2]=0.f; sacc[i][3]=0.f; }
        #pragma unroll
        for (int kb = 0; kb < 8; kb++) {
            #pragma unroll
            for (int nf2 = 0; nf2 < 4; nf2++) {
                uint32_t t[4];
                ldsm4(t, ok + (nf2*16 + rB)*272 + (cB + 2*kb)*16);
                uint32_t b0[2] = {t[0], t[1]}, b1[2] = {t[2], t[3]};
                mma16816(sacc[2*nf2],   qf[kb], b0);
                mma16816(sacc[2*nf2+1], qf[kb], b1);
            }
        }

        // ---- scale + bias + mask, online softmax ----
        float p[8][4];
        float rmax0 = -1e30f, rmax1 = -1e30f;
        #pragma unroll
        for (int nf = 0; nf < 8; nf++) {
            const int gc = kt*64 + nf*8 + (lane & 3)*2;
            float2 bb0 = *(const float2*)(bias + ((size_t)h*S_ + gr0)*S_ + gc);
            float2 mk0 = *(const float2*)(mask + (size_t)gr0*S_ + gc);
            float2 bb1 = *(const float2*)(bias + ((size_t)h*S_ + gr1)*S_ + gc);
            float2 mk1 = *(const float2*)(mask + (size_t)gr1*S_ + gc);
            p[nf][0] = sacc[nf][0]*SCALE_ + (bb0.x + mk0.x);
            p[nf][1] = sacc[nf][1]*SCALE_ + (bb0.y + mk0.y);
            p[nf][2] = sacc[nf][2]*SCALE_ + (bb1.x + mk1.x);
            p[nf][3] = sacc[nf][3]*SCALE_ + (bb1.y + mk1.y);
            rmax0 = fmaxf(rmax0, fmaxf(p[nf][0], p[nf][1]));
            rmax1 = fmaxf(rmax1, fmaxf(p[nf][2], p[nf][3]));
        }
        rmax0 = fmaxf(rmax0, __shfl_xor_sync(0xffffffffu, rmax0, 1));
        rmax0 = fmaxf(rmax0, __shfl_xor_sync(0xffffffffu, rmax0, 2));
        rmax1 = fmaxf(rmax1, __shfl_xor_sync(0xffffffffu, rmax1, 1));
        rmax1 = fmaxf(rmax1, __shfl_xor_sync(0xffffffffu, rmax1, 2));

        const float mn0 = fmaxf(m0, rmax0), mn1 = fmaxf(m1, rmax1);
        const float al0 = __expf(m0 - mn0), al1 = __expf(m1 - mn1);
        m0 = mn0; m1 = mn1;

        float rs0 = 0.f, rs1 = 0.f;
        #pragma unroll
        for (int nf = 0; nf < 8; nf++) {
            p[nf][0] = __expf(p[nf][0] - mn0);
            p[nf][1] = __expf(p[nf][1] - mn0);
            p[nf][2] = __expf(p[nf][2] - mn1);
            p[nf][3] = __expf(p[nf][3] - mn1);
            rs0 += p[nf][0] + p[nf][1];
            rs1 += p[nf][2] + p[nf][3];
        }
        rs0 += __shfl_xor_sync(0xffffffffu, rs0, 1);
        rs0 += __shfl_xor_sync(0xffffffffu, rs0, 2);
        rs1 += __shfl_xor_sync(0xffffffffu, rs1, 1);
        rs1 += __shfl_xor_sync(0xffffffffu, rs1, 2);
        l0 = l0 * al0 + rs0;
        l1 = l1 * al1 + rs1;

        #pragma unroll
        for (int i = 0; i < 16; i++) {
            oacc[i][0] *= al0; oacc[i][1] *= al0;
            oacc[i][2] *= al1; oacc[i][3] *= al1;
        }

        // ---- store P (fp16) to smem, pitch 144 ----
        {
            const uint32_t pr0 = sb + (w*16 + (lane>>2))*144 + (lane & 3)*4;
            #pragma unroll
            for (int nf = 0; nf < 8; nf++) {
                asm volatile("st.shared.u32 [%0], %1;" :: "r"(pr0 + nf*16), "r"(pack2h(p[nf][0], p[nf][1])) : "memory");
                asm volatile("st.shared.u32 [%0], %1;" :: "r"(pr0 + 8*144 + nf*16), "r"(pack2h(p[nf][2], p[nf][3])) : "memory");
            }
        }
        __syncwarp();

        // ---- O += P @ V (k = 64 kv -> 4 ksteps) ----
        #pragma unroll
        for (int kb = 0; kb < 4; kb++) {
            uint32_t pa[4];
            ldsm4(pa, sb + (w*16 + rA)*144 + (cA + 2*kb)*16);
            #pragma unroll
            for (int nf2 = 0; nf2 < 8; nf2++) {
                uint32_t t[4];
                ldsm4(t, ov + (nf2*16 + rB)*144 + (cB + 2*kb)*16);
                uint32_t b0[2] = {t[0], t[1]}, b1[2] = {t[2], t[3]};
                mma16816(oacc[2*nf2],   pa, b0);
                mma16816(oacc[2*nf2+1], pa, b1);
            }
        }
        __syncthreads();
        if (kt + 2 < 32) loadKV(kt + 2, buf);
    }

    // ---- output: att = half(O / l) ----
    const float inv0 = 1.0f / l0, inv1 = 1.0f / l1;
    __half* o0 = g_att + (size_t)(b*S_ + gr0) * DIM_ + h*HD_;
    __half* o1 = g_att + (size_t)(b*S_ + gr1) * DIM_ + h*HD_;
    #pragma unroll
    for (int nfd = 0; nfd < 16; nfd++) {
        const int dc = nfd*8 + (lane & 3)*2;
        *(uint32_t*)(o0 + dc) = pack2h(oacc[nfd][0]*inv0, oacc[nfd][1]*inv0);
        *(uint32_t*)(o1 + dc) = pack2h(oacc[nfd][2]*inv1, oacc[nfd][3]*inv1);
    }
}

// ---------------- weight copy fp32 -> fp16 ----------------
__global__ __launch_bounds__(256) void cvt_h(const float* __restrict__ src,
                                             __half* __restrict__ dst, size_t n4)
{
    const size_t stride = (size_t)gridDim.x * 256;
    for (size_t i = (size_t)blockIdx.x * 256 + threadIdx.x; i < n4; i += stride) {
        float4 v = *(const float4*)(src + i * 4);
        __half2* d2 = (__half2*)(dst + i * 4);
        d2[0] = __floats2half2_rn(v.x, v.y);
        d2[1] = __floats2half2_rn(v.z, v.w);
    }
}

// ---------------- interleave w1/w3 rows -> fp16 ----------------
__global__ __launch_bounds__(256) void ilv_w13(const float* __restrict__ w1,
                                               const float* __restrict__ w3,
                                               __half* __restrict__ dst)
{
    const size_t idx = (size_t)blockIdx.x * 256 + threadIdx.x;   // 2*HID*512
    const size_t rr = idx >> 9, sg = idx & 511;
    const float* src = (rr & 1) ? w3 : w1;
    float4 v = *(const float4*)(src + (rr >> 1) * DIM_ + sg * 4);
    __half2* d2 = (__half2*)(dst + rr * DIM_ + sg * 4);
    d2[0] = __floats2half2_rn(v.x, v.y);
    d2[1] = __floats2half2_rn(v.z, v.w);
}

// ---------------- rmsnorm: fp32 in -> fp16 out ----------------
__global__ __launch_bounds__(256) void rmsnorm_k(const float* __restrict__ x,
                                                 const float* __restrict__ w,
                                                 __half* __restrict__ o)
{
    __shared__ float red[8];
    const size_t row = blockIdx.x;
    const float* xr = x + row * (size_t)DIM_;
    const int tid = threadIdx.x;
    float4 v0 = *(const float4*)(xr + tid*4);
    float4 v1 = *(const float4*)(xr + 1024 + tid*4);
    float s = v0.x*v0.x + v0.y*v0.y + v0.z*v0.z + v0.w*v0.w
            + v1.x*v1.x + v1.y*v1.y + v1.z*v1.z + v1.w*v1.w;
    #pragma unroll
    for (int off = 16; off > 0; off >>= 1) s += __shfl_xor_sync(0xffffffffu, s, off);
    if ((tid & 31) == 0) red[tid >> 5] = s;
    __syncthreads();
    s = red[0]+red[1]+red[2]+red[3]+red[4]+red[5]+red[6]+red[7];
    const float r = rsqrtf(s * (1.0f/DIM_) + EPS_);
    float4 w0 = *(const float4*)(w + tid*4);
    float4 w1 = *(const float4*)(w + 1024 + tid*4);
    __half2* orow = (__half2*)(o + row * (size_t)DIM_);
    orow[tid*2]          = __floats2half2_rn(v0.x*r*w0.x, v0.y*r*w0.y);
    orow[tid*2+1]        = __floats2half2_rn(v0.z*r*w0.z, v0.w*r*w0.w);
    orow[512 + tid*2]    = __floats2half2_rn(v1.x*r*w1.x, v1.y*r*w1.y);
    orow[512 + tid*2+1]  = __floats2half2_rn(v1.z*r*w1.z, v1.w*r*w1.w);
}

// ---------------- V transpose: qkv v-part -> vt [b][h*128+d][s] (fp16) ----------------
__global__ __launch_bounds__(256) void transpose_v()
{
    __shared__ __half t[32][33];
    const int b  = blockIdx.z;
    const int s0 = blockIdx.x * 32, j0 = blockIdx.y * 32;
    const int x = threadIdx.x & 31, y = threadIdx.x >> 5;
    #pragma unroll
    for (int yy = y; yy < 32; yy += 8)
        t[yy][x] = g_qkv[(size_t)(b*S_ + s0 + yy) * (3*DIM_) + 2*DIM_ + j0 + x];
    __syncthreads();
    #pragma unroll
    for (int yy = y; yy < 32; yy += 8)
        g_vt[(size_t)(b*DIM_ + j0 + yy) * S_ + s0 + x] = t[x][yy];
}

// ---------------- launch ----------------
extern "C" void kernel_launch(void* const* d_in, const int* in_sizes, int n_in,
                              void* d_out, int out_size)
{
    (void)in_sizes; (void)n_in; (void)out_size;
    const float* x    = (const float*)d_in[0];
    const float* mask = (const float*)d_in[1];
    const float* bias = (const float*)d_in[2];
    const float* wq   = (const float*)d_in[3];
    const float* wk   = (const float*)d_in[4];
    const float* wv   = (const float*)d_in[5];
    const float* wo   = (const float*)d_in[6];
    const float* w1   = (const float*)d_in[7];
    const float* w2   = (const float*)d_in[8];
    const float* w3   = (const float*)d_in[9];
    const float* anw  = (const float*)d_in[10];
    const float* fnw  = (const float*)d_in[11];
    float* out = (float*)d_out;

    __half *h, *qkv, *att, *f, *ff, *cwqkv, *cwo, *cw13, *cw2;
    float *h1;
    cudaGetSymbolAddress((void**)&h,    g_h);
    cudaGetSymbolAddress((void**)&qkv,  g_qkv);
    cudaGetSymbolAddress((void**)&att,  g_att);
    cudaGetSymbolAddress((void**)&h1,   g_h1);
    cudaGetSymbolAddress((void**)&f,    g_f);
    cudaGetSymbolAddress((void**)&ff,   g_ff);
    cudaGetSymbolAddress((void**)&cwqkv,g_wqkv);
    cudaGetSymbolAddress((void**)&cwo,  g_wo);
    cudaGetSymbolAddress((void**)&cw13, g_w13);
    cudaGetSymbolAddress((void**)&cw2,  g_w2);

    const int SMH = NSTAGE * (128 + 256) * 128 + 256;   // ~192.3 KB
    cudaFuncSetAttribute(mm_h<256>, cudaFuncAttributeMaxDynamicSharedMemorySize, SMH);
    cudaFuncSetAttribute(flash_k, cudaFuncAttributeMaxDynamicSharedMemorySize, FL_SMEM);

    // weight prep (fp16; qkv concat, w1/w3 interleave)
    cvt_h<<<1024, 256>>>(wq, cwqkv,                       (size_t)DIM_*DIM_/4);
    cvt_h<<<1024, 256>>>(wk, cwqkv + (size_t)DIM_*DIM_,   (size_t)DIM_*DIM_/4);
    cvt_h<<<1024, 256>>>(wv, cwqkv + (size_t)2*DIM_*DIM_, (size_t)DIM_*DIM_/4);
    cvt_h<<<1024, 256>>>(wo, cwo,                         (size_t)DIM_*DIM_/4);
    ilv_w13<<<(unsigned)((size_t)2*HID_*512/256), 256>>>(w1, w3, cw13);
    cvt_h<<<1024, 256>>>(w2, cw2,                         (size_t)DIM_*HID_/4);

    // --- attention ---
    rmsnorm_k<<<M_, 256>>>(x, anw, h);
    mm_h<256><<<dim3(3*DIM_/256, M_/128), 256, SMH>>>(
        h, cwqkv, qkv, nullptr, DIM_, DIM_, DIM_, 3*DIM_, 1);
    transpose_v<<<dim3(S_/32, DIM_/32, B_), 256>>>();
    flash_k<<<dim3(S_/128, B_*NH_), 256, FL_SMEM>>>(bias, mask);
    mm_h<256><<<dim3(DIM_/256, M_/128), 256, SMH>>>(
        att, cwo, h1, x, DIM_, DIM_, DIM_, DIM_, 2);

    // --- FFN ---
    rmsnorm_k<<<M_, 256>>>(h1, fnw, f);
    mm_h<256><<<dim3(2*HID_/256, M_/128), 256, SMH>>>(
        f, cw13, ff, nullptr, DIM_, DIM_, DIM_, HID_, 4);
    mm_h<256><<<dim3(DIM_/256, M_/128), 256, SMH>>>(
        ff, cw2, out, h1, HID_, HID_, HID_, DIM_, 2);
}

// round 7
// speedup vs baseline: 7.5541x; 1.1271x over previous
#include <cuda_runtime.h>
#include <cuda_fp16.h>
#include <math.h>
#include <stdint.h>

// ---------------- problem constants ----------------
#define B_    2
#define S_    2048
#define DIM_  2048
#define NH_   16
#define HD_   128
#define HID_  5632
#define M_    (B_*S_)
#define EPS_  1e-5f
#define SCALE_ 0.08838834764831845f   // 1/sqrt(128)

// ---------------- scratch (device globals; no allocation) ----------------
__device__ __half g_h   [(size_t)M_*DIM_];
__device__ __half g_qkv [(size_t)M_*2*DIM_];          // [m][q|k]  (row stride 2*DIM)
__device__ __half g_vt  [(size_t)NH_*HD_*M_];         // [h*128+d][b*S+s]
__device__ __half g_att [(size_t)M_*DIM_];
__device__ float  g_h1  [(size_t)M_*DIM_];
__device__ __half g_f   [(size_t)M_*DIM_];
__device__ __half g_ff  [(size_t)M_*HID_];
__device__ __half g_bm16[(size_t)NH_*S_*S_];          // half(bias + mask)
// fp16 weight copies
__device__ __half g_wqkv[(size_t)3*DIM_*DIM_];        // wq | wk | wv
__device__ __half g_wo  [(size_t)DIM_*DIM_];
__device__ __half g_w13 [(size_t)2*HID_*DIM_];        // interleaved rows: 2j=w1[j], 2j+1=w3[j]
__device__ __half g_w2  [(size_t)DIM_*HID_];

// ---------------- helpers ----------------
__device__ __forceinline__ uint32_t smem_u32(const void* p){
    uint32_t a;
    asm("{ .reg .u64 t; cvta.to.shared.u64 t, %1; cvt.u32.u64 %0, t; }" : "=r"(a) : "l"(p));
    return a;
}
__device__ __forceinline__ uint32_t swz(uint32_t x){ return x ^ ((x >> 3) & 0x70); }
#define CP16(dst, src) asm volatile("cp.async.cg.shared.global [%0], [%1], 16;" :: "r"(dst), "l"(src))

__device__ __forceinline__ void ldsm4(uint32_t* r, uint32_t addr){
    asm volatile("ldmatrix.sync.aligned.m8n8.x4.shared.b16 {%0,%1,%2,%3}, [%4];"
        : "=r"(r[0]),"=r"(r[1]),"=r"(r[2]),"=r"(r[3]) : "r"(addr));
}
__device__ __forceinline__ void mma16816(float* c, const uint32_t* a, const uint32_t* b){
    asm volatile("mma.sync.aligned.m16n8k16.row.col.f32.f16.f16.f32 "
        "{%0,%1,%2,%3}, {%4,%5,%6,%7}, {%8,%9}, {%0,%1,%2,%3};"
        : "+f"(c[0]),"+f"(c[1]),"+f"(c[2]),"+f"(c[3])
        : "r"(a[0]),"r"(a[1]),"r"(a[2]),"r"(a[3]), "r"(b[0]),"r"(b[1]));
}
__device__ __forceinline__ uint32_t pack2h(float a, float b){
    __half2 h = __floats2half2_rn(a, b);
    return *reinterpret_cast<uint32_t*>(&h);
}

// =====================================================================
// fp16 mma.sync GEMM: C[m,n] (+epi) = sum_k A[m,k]*B[n,k]
// CTA 128 x BN, BK=64 (128B rows, SW128), 4-stage cp.async.
// epi: 1 half-out, 2 fp32-out + residual Rb, 4 swiglu-interleaved (N/2 cols),
//      5 half-out with SCALE_ on cols < DIM_ (q part of qk GEMM)
// =====================================================================
#define NSTAGE 4

template<int BN>
__global__ __launch_bounds__(256, 1) void mm_h(
    const __half* __restrict__ A, const __half* __restrict__ B, void* __restrict__ Cv,
    const float* __restrict__ Rb,
    int K, int lda, int ldb, int ldc, int epi)
{
    constexpr int WN = BN / 4;
    constexpr int NF = WN / 8;
    constexpr int STAGE = (128 + BN) * 128;
    constexpr int BI = BN / 32;

    extern __shared__ char smem[];
    const uint32_t sbase = (smem_u32(smem) + 127u) & ~127u;

    const int tid = threadIdx.x;
    const int wid = tid >> 5, lane = tid & 31;
    const int wm = (wid >> 2) * 64;
    const int wn = (wid & 3) * WN;
    const int bm = blockIdx.y * 128, bn = blockIdx.x * BN;

    const int tA = lane >> 3;
    const int rA = (tA & 1) * 8 + (lane & 7);
    const int cA = tA >> 1;
    const int rB = (tA >> 1) * 8 + (lane & 7);
    const int cB = tA & 1;

    float acc[4][NF][4];
    #pragma unroll
    for (int i = 0; i < 4; i++)
        #pragma unroll
        for (int j = 0; j < NF; j++)
            { acc[i][j][0]=0.f; acc[i][j][1]=0.f; acc[i][j][2]=0.f; acc[i][j][3]=0.f; }

    const int nch = K >> 6;

    auto produce = [&](int c) {
        const uint32_t sA = sbase + (c & (NSTAGE-1)) * STAGE;
        const uint32_t sB = sA + 128 * 128;
        const int k0 = c << 6;
        #pragma unroll
        for (int i = 0; i < 4; i++) {
            int idx = tid + 256 * i; int row = idx >> 3, seg = idx & 7;
            CP16(sA + swz(row * 128 + seg * 16),
                 A + (size_t)(bm + row) * lda + k0 + seg * 8);
        }
        #pragma unroll
        for (int i = 0; i < BI; i++) {
            int idx = tid + 256 * i; int row = idx >> 3, seg = idx & 7;
            CP16(sB + swz(row * 128 + seg * 16),
                 B + (size_t)(bn + row) * ldb + k0 + seg * 8);
        }
        asm volatile("cp.async.commit_group;" ::: "memory");
    };

    const int pre = nch < 3 ? nch : 3;
    for (int i = 0; i < pre; i++) produce(i);

    for (int c = 0; c < nch; c++) {
        if (c < nch - 2)       asm volatile("cp.async.wait_group 2;" ::: "memory");
        else if (c == nch - 2) asm volatile("cp.async.wait_group 1;" ::: "memory");
        else                   asm volatile("cp.async.wait_group 0;" ::: "memory");
        __syncthreads();
        if (c + 3 < nch) produce(c + 3);

        const uint32_t sA = sbase + (c & (NSTAGE-1)) * STAGE;
        const uint32_t sB = sA + 128 * 128;
        #pragma unroll
        for (int kk = 0; kk < 4; kk++) {
            uint32_t a[4][4];
            #pragma unroll
            for (int mf = 0; mf < 4; mf++) {
                const int row = wm + mf * 16 + rA;
                ldsm4(a[mf], sA + row * 128 + (((cA + 2*kk) ^ (rA & 7)) * 16));
            }
            uint32_t b[NF][2];
            #pragma unroll
            for (int nf2 = 0; nf2 < NF/2; nf2++) {
                uint32_t t[4];
                const int row = wn + nf2 * 16 + rB;
                ldsm4(t, sB + row * 128 + (((cB + 2*kk) ^ (rB & 7)) * 16));
                b[2*nf2][0]=t[0]; b[2*nf2][1]=t[1];
                b[2*nf2+1][0]=t[2]; b[2*nf2+1][1]=t[3];
            }
            #pragma unroll
            for (int mf = 0; mf < 4; mf++)
                #pragma unroll
                for (int nf = 0; nf < NF; nf++)
                    mma16816(acc[mf][nf], a[mf], b[nf]);
        }
    }
    __syncthreads();

    #pragma unroll
    for (int mf = 0; mf < 4; mf++) {
        const int r0 = bm + wm + mf * 16 + (lane >> 2);
        const int r1 = r0 + 8;
        #pragma unroll
        for (int nf = 0; nf < NF; nf++) {
            const int col = bn + wn + nf * 8 + (lane & 3) * 2;
            float2 v0 = make_float2(acc[mf][nf][0], acc[mf][nf][1]);
            float2 v1 = make_float2(acc[mf][nf][2], acc[mf][nf][3]);
            if (epi == 4) {
                __half* C = (__half*)Cv;
                float a0 = v0.x / (1.0f + __expf(-v0.x)) * v0.y;
                float a1 = v1.x / (1.0f + __expf(-v1.x)) * v1.y;
                C[(size_t)r0 * ldc + (col >> 1)] = __float2half_rn(a0);
                C[(size_t)r1 * ldc + (col >> 1)] = __float2half_rn(a1);
            } else if (epi == 1) {
                __half* C = (__half*)Cv;
                *(uint32_t*)(C + (size_t)r0 * ldc + col) = pack2h(v0.x, v0.y);
                *(uint32_t*)(C + (size_t)r1 * ldc + col) = pack2h(v1.x, v1.y);
            } else if (epi == 5) {
                __half* C = (__half*)Cv;
                const float sc = (col < DIM_) ? SCALE_ : 1.0f;
                *(uint32_t*)(C + (size_t)r0 * ldc + col) = pack2h(v0.x*sc, v0.y*sc);
                *(uint32_t*)(C + (size_t)r1 * ldc + col) = pack2h(v1.x*sc, v1.y*sc);
            } else {
                float* C = (float*)Cv;
                float2 a0 = *(const float2*)(Rb + (size_t)r0 * ldc + col);
                float2 a1 = *(const float2*)(Rb + (size_t)r1 * ldc + col);
                v0.x += a0.x; v0.y += a0.y;
                v1.x += a1.x; v1.y += a1.y;
                *(float2*)(C + (size_t)r0 * ldc + col) = v0;
                *(float2*)(C + (size_t)r1 * ldc + col) = v1;
            }
        }
    }
}

// =====================================================================
// Flash attention (fp16 in, fp32 softmax/accum). Q pre-scaled by 1/sqrt(d).
// CTA = 128 q rows x 1 head, 32 kv tiles of 64. 8 warps, warp = 16 q rows.
// smem: Q/P @0 (pitch 272, 34816) | K x2 (pitch 272, 17408 ea) | V x2 (pitch 144, 18432 ea)
// =====================================================================
#define FL_SMEM (106624)

__global__ __launch_bounds__(256, 2) void flash_k()
{
    extern __shared__ char smem[];
    const uint32_t sb = (smem_u32(smem) + 127u) & ~127u;

    const int tid = threadIdx.x;
    const int w = tid >> 5, lane = tid & 31;
    const int tA = lane >> 3;
    const int rA = (tA & 1) * 8 + (lane & 7);
    const int cA = tA >> 1;
    const int rB = (tA >> 1) * 8 + (lane & 7);
    const int cB = tA & 1;

    const int z = blockIdx.y, b = z >> 4, h = z & 15;
    const int bm = blockIdx.x * 128;

    const __half* qbase = g_qkv + (size_t)(b*S_ + bm) * (2*DIM_) + h*HD_;
    const __half* kbase = g_qkv + (size_t)(b*S_) * (2*DIM_) + DIM_ + h*HD_;
    const __half* vbase = g_vt + (size_t)h * HD_ * M_ + b*S_;   // row stride M_
    const __half* bmb   = g_bm16 + (size_t)h * S_ * S_;

    auto loadKV = [&](int kt, int buf) {
        const uint32_t ok = sb + 34816 + buf * 17408;
        const uint32_t ov = sb + 69632 + buf * 18432;
        #pragma unroll
        for (int i = 0; i < 4; i++) {       // K: 64 rows x 16 segs
            int idx = tid + 256*i; int r = idx >> 4, sg = idx & 15;
            CP16(ok + r*272 + sg*16, kbase + (size_t)(kt*64 + r) * (2*DIM_) + sg*8);
        }
        #pragma unroll
        for (int i = 0; i < 4; i++) {       // V: 128 d-rows x 8 segs
            int idx = tid + 256*i; int r = idx >> 3, sg = idx & 7;
            CP16(ov + r*144 + sg*16, vbase + (size_t)r * M_ + kt*64 + sg*8);
        }
        asm volatile("cp.async.commit_group;" ::: "memory");
    };

    // Q tile -> smem (128 rows x 16 segs, pitch 272)
    #pragma unroll
    for (int i = 0; i < 8; i++) {
        int idx = tid + 256*i; int r = idx >> 4, sg = idx & 15;
        CP16(sb + r*272 + sg*16, qbase + (size_t)r * (2*DIM_) + sg*8);
    }
    asm volatile("cp.async.commit_group;" ::: "memory");
    loadKV(0, 0);
    loadKV(1, 1);
    asm volatile("cp.async.wait_group 2;" ::: "memory");
    __syncthreads();

    uint32_t qf[8][4];
    #pragma unroll
    for (int kb = 0; kb < 8; kb++)
        ldsm4(qf[kb], sb + (w*16 + rA)*272 + (cA + 2*kb)*16);
    __syncthreads();

    const int gr0 = bm + w*16 + (lane >> 2);
    const int gr1 = gr0 + 8;

    float m0 = -1e30f, m1 = -1e30f, l0 = 0.f, l1 = 0.f;
    float oacc[16][4];
    #pragma unroll
    for (int i = 0; i < 16; i++)
        { oacc[i][0]=0.f; oacc[i][1]=0.f; oacc[i][2]=0.f; oacc[i][3]=0.f; }

    for (int kt = 0; kt < 32; kt++) {
        if (kt < 31) asm volatile("cp.async.wait_group 1;" ::: "memory");
        else         asm volatile("cp.async.wait_group 0;" ::: "memory");
        __syncthreads();
        const int buf = kt & 1;
        const uint32_t ok = sb + 34816 + buf * 17408;
        const uint32_t ov = sb + 69632 + buf * 18432;

        // ---- S = Q @ K^T ----
        float sacc[8][4];
        #pragma unroll
        for (int i = 0; i < 8; i++)
            { sacc[i][0]=0.f; sacc[i][1]=0.f; sacc[i][2]=0.f; sacc[i][3]=0.f; }
        #pragma unroll
        for (int kb = 0; kb < 8; kb++) {
            #pragma unroll
            for (int nf2 = 0; nf2 < 4; nf2++) {
                uint32_t t[4];
                ldsm4(t, ok + (nf2*16 + rB)*272 + (cB + 2*kb)*16);
                uint32_t b0[2] = {t[0], t[1]}, b1[2] = {t[2], t[3]};
                mma16816(sacc[2*nf2],   qf[kb], b0);
                mma16816(sacc[2*nf2+1], qf[kb], b1);
            }
        }

        // ---- + (bias+mask) [fp16 precomputed], online softmax ----
        float p[8][4];
        float rmax0 = -1e30f, rmax1 = -1e30f;
        #pragma unroll
        for (int nf = 0; nf < 8; nf++) {
            const int gc = kt*64 + nf*8 + (lane & 3)*2;
            float2 f0 = __half22float2(*(const __half2*)(bmb + (size_t)gr0*S_ + gc));
            float2 f1 = __half22float2(*(const __half2*)(bmb + (size_t)gr1*S_ + gc));
            p[nf][0] = sacc[nf][0] + f0.x;
            p[nf][1] = sacc[nf][1] + f0.y;
            p[nf][2] = sacc[nf][2] + f1.x;
            p[nf][3] = sacc[nf][3] + f1.y;
            rmax0 = fmaxf(rmax0, fmaxf(p[nf][0], p[nf][1]));
            rmax1 = fmaxf(rmax1, fmaxf(p[nf][2], p[nf][3]));
        }
        rmax0 = fmaxf(rmax0, __shfl_xor_sync(0xffffffffu, rmax0, 1));
        rmax0 = fmaxf(rmax0, __shfl_xor_sync(0xffffffffu, rmax0, 2));
        rmax1 = fmaxf(rmax1, __shfl_xor_sync(0xffffffffu, rmax1, 1));
        rmax1 = fmaxf(rmax1, __shfl_xor_sync(0xffffffffu, rmax1, 2));

        const float mn0 = fmaxf(m0, rmax0), mn1 = fmaxf(m1, rmax1);
        const float al0 = __expf(m0 - mn0), al1 = __expf(m1 - mn1);
        m0 = mn0; m1 = mn1;

        float rs0 = 0.f, rs1 = 0.f;
        #pragma unroll
        for (int nf = 0; nf < 8; nf++) {
            p[nf][0] = __expf(p[nf][0] - mn0);
            p[nf][1] = __expf(p[nf][1] - mn0);
            p[nf][2] = __expf(p[nf][2] - mn1);
            p[nf][3] = __expf(p[nf][3] - mn1);
            rs0 += p[nf][0] + p[nf][1];
            rs1 += p[nf][2] + p[nf][3];
        }
        rs0 += __shfl_xor_sync(0xffffffffu, rs0, 1);
        rs0 += __shfl_xor_sync(0xffffffffu, rs0, 2);
        rs1 += __shfl_xor_sync(0xffffffffu, rs1, 1);
        rs1 += __shfl_xor_sync(0xffffffffu, rs1, 2);
        l0 = l0 * al0 + rs0;
        l1 = l1 * al1 + rs1;

        #pragma unroll
        for (int i = 0; i < 16; i++) {
            oacc[i][0] *= al0; oacc[i][1] *= al0;
            oacc[i][2] *= al1; oacc[i][3] *= al1;
        }

        // ---- store P (fp16) to smem, pitch 144 ----
        {
            const uint32_t pr0 = sb + (w*16 + (lane>>2))*144 + (lane & 3)*4;
            #pragma unroll
            for (int nf = 0; nf < 8; nf++) {
                asm volatile("st.shared.u32 [%0], %1;" :: "r"(pr0 + nf*16), "r"(pack2h(p[nf][0], p[nf][1])) : "memory");
                asm volatile("st.shared.u32 [%0], %1;" :: "r"(pr0 + 8*144 + nf*16), "r"(pack2h(p[nf][2], p[nf][3])) : "memory");
            }
        }
        __syncwarp();

        // ---- O += P @ V ----
        #pragma unroll
        for (int kb = 0; kb < 4; kb++) {
            uint32_t pa[4];
            ldsm4(pa, sb + (w*16 + rA)*144 + (cA + 2*kb)*16);
            #pragma unroll
            for (int nf2 = 0; nf2 < 8; nf2++) {
                uint32_t t[4];
                ldsm4(t, ov + (nf2*16 + rB)*144 + (cB + 2*kb)*16);
                uint32_t b0[2] = {t[0], t[1]}, b1[2] = {t[2], t[3]};
                mma16816(oacc[2*nf2],   pa, b0);
                mma16816(oacc[2*nf2+1], pa, b1);
            }
        }
        __syncthreads();
        if (kt + 2 < 32) loadKV(kt + 2, buf);
    }

    const float inv0 = 1.0f / l0, inv1 = 1.0f / l1;
    __half* o0 = g_att + (size_t)(b*S_ + gr0) * DIM_ + h*HD_;
    __half* o1 = g_att + (size_t)(b*S_ + gr1) * DIM_ + h*HD_;
    #pragma unroll
    for (int nfd = 0; nfd < 16; nfd++) {
        const int dc = nfd*8 + (lane & 3)*2;
        *(uint32_t*)(o0 + dc) = pack2h(oacc[nfd][0]*inv0, oacc[nfd][1]*inv0);
        *(uint32_t*)(o1 + dc) = pack2h(oacc[nfd][2]*inv1, oacc[nfd][3]*inv1);
    }
}

// ---------------- weight copy fp32 -> fp16 ----------------
__global__ __launch_bounds__(256) void cvt_h(const float* __restrict__ src,
                                             __half* __restrict__ dst, size_t n4)
{
    const size_t stride = (size_t)gridDim.x * 256;
    for (size_t i = (size_t)blockIdx.x * 256 + threadIdx.x; i < n4; i += stride) {
        float4 v = *(const float4*)(src + i * 4);
        __half2* d2 = (__half2*)(dst + i * 4);
        d2[0] = __floats2half2_rn(v.x, v.y);
        d2[1] = __floats2half2_rn(v.z, v.w);
    }
}

// ---------------- bm16 = half(bias + mask) ----------------
__global__ __launch_bounds__(256) void prep_bm(const float* __restrict__ bias,
                                               const float* __restrict__ mask,
                                               __half* __restrict__ dst)
{
    const size_t n4 = (size_t)NH_*S_*S_/4;
    const size_t stride = (size_t)gridDim.x * 256;
    for (size_t i = (size_t)blockIdx.x * 256 + threadIdx.x; i < n4; i += stride) {
        float4 bv = ((const float4*)bias)[i];
        float4 mv = ((const float4*)mask)[i & ((size_t)S_*S_/4 - 1)];
        __half2* d2 = (__half2*)(dst + i * 4);
        d2[0] = __floats2half2_rn(bv.x + mv.x, bv.y + mv.y);
        d2[1] = __floats2half2_rn(bv.z + mv.z, bv.w + mv.w);
    }
}

// ---------------- interleave w1/w3 rows -> fp16 ----------------
__global__ __launch_bounds__(256) void ilv_w13(const float* __restrict__ w1,
                                               const float* __restrict__ w3,
                                               __half* __restrict__ dst)
{
    const size_t idx = (size_t)blockIdx.x * 256 + threadIdx.x;   // 2*HID*512
    const size_t rr = idx >> 9, sg = idx & 511;
    const float* src = (rr & 1) ? w3 : w1;
    float4 v = *(const float4*)(src + (rr >> 1) * DIM_ + sg * 4);
    __half2* d2 = (__half2*)(dst + rr * DIM_ + sg * 4);
    d2[0] = __floats2half2_rn(v.x, v.y);
    d2[1] = __floats2half2_rn(v.z, v.w);
}

// ---------------- rmsnorm: fp32 in -> fp16 out ----------------
__global__ __launch_bounds__(256) void rmsnorm_k(const float* __restrict__ x,
                                                 const float* __restrict__ w,
                                                 __half* __restrict__ o)
{
    __shared__ float red[8];
    const size_t row = blockIdx.x;
    const float* xr = x + row * (size_t)DIM_;
    const int tid = threadIdx.x;
    float4 v0 = *(const float4*)(xr + tid*4);
    float4 v1 = *(const float4*)(xr + 1024 + tid*4);
    float s = v0.x*v0.x + v0.y*v0.y + v0.z*v0.z + v0.w*v0.w
            + v1.x*v1.x + v1.y*v1.y + v1.z*v1.z + v1.w*v1.w;
    #pragma unroll
    for (int off = 16; off > 0; off >>= 1) s += __shfl_xor_sync(0xffffffffu, s, off);
    if ((tid & 31) == 0) red[tid >> 5] = s;
    __syncthreads();
    s = red[0]+red[1]+red[2]+red[3]+red[4]+red[5]+red[6]+red[7];
    const float r = rsqrtf(s * (1.0f/DIM_) + EPS_);
    float4 w0 = *(const float4*)(w + tid*4);
    float4 w1 = *(const float4*)(w + 1024 + tid*4);
    __half2* orow = (__half2*)(o + row * (size_t)DIM_);
    orow[tid*2]          = __floats2half2_rn(v0.x*r*w0.x, v0.y*r*w0.y);
    orow[tid*2+1]        = __floats2half2_rn(v0.z*r*w0.z, v0.w*r*w0.w);
    orow[512 + tid*2]    = __floats2half2_rn(v1.x*r*w1.x, v1.y*r*w1.y);
    orow[512 + tid*2+1]  = __floats2half2_rn(v1.z*r*w1.z, v1.w*r*w1.w);
}

// ---------------- launch ----------------
extern "C" void kernel_launch(void* const* d_in, const int* in_sizes, int n_in,
                              void* d_out, int out_size)
{
    (void)in_sizes; (void)n_in; (void)out_size;
    const float* x    = (const float*)d_in[0];
    const float* mask = (const float*)d_in[1];
    const float* bias = (const float*)d_in[2];
    const float* wq   = (const float*)d_in[3];
    const float* wk   = (const float*)d_in[4];
    const float* wv   = (const float*)d_in[5];
    const float* wo   = (const float*)d_in[6];
    const float* w1   = (const float*)d_in[7];
    const float* w2   = (const float*)d_in[8];
    const float* w3   = (const float*)d_in[9];
    const float* anw  = (const float*)d_in[10];
    const float* fnw  = (const float*)d_in[11];
    float* out = (float*)d_out;

    __half *h, *qkv, *vt, *att, *f, *ff, *bm16, *cwqkv, *cwo, *cw13, *cw2;
    float *h1;
    cudaGetSymbolAddress((void**)&h,    g_h);
    cudaGetSymbolAddress((void**)&qkv,  g_qkv);
    cudaGetSymbolAddress((void**)&vt,   g_vt);
    cudaGetSymbolAddress((void**)&att,  g_att);
    cudaGetSymbolAddress((void**)&h1,   g_h1);
    cudaGetSymbolAddress((void**)&f,    g_f);
    cudaGetSymbolAddress((void**)&ff,   g_ff);
    cudaGetSymbolAddress((void**)&bm16, g_bm16);
    cudaGetSymbolAddress((void**)&cwqkv,g_wqkv);
    cudaGetSymbolAddress((void**)&cwo,  g_wo);
    cudaGetSymbolAddress((void**)&cw13, g_w13);
    cudaGetSymbolAddress((void**)&cw2,  g_w2);

    const int SMH = NSTAGE * (128 + 256) * 128 + 256;   // ~192.3 KB
    cudaFuncSetAttribute(mm_h<256>, cudaFuncAttributeMaxDynamicSharedMemorySize, SMH);
    cudaFuncSetAttribute(flash_k, cudaFuncAttributeMaxDynamicSharedMemorySize, FL_SMEM);

    // ---- side stream for prep work (fork-join; objects intentionally not
    //      destroyed here: destroying mid-capture would invalidate the graph) ----
    cudaStream_t s1;
    cudaStreamCreate(&s1);
    cudaEvent_t eF, eQK, eV, eBM, eWo, eW13, eW2;
    cudaEventCreateWithFlags(&eF,   cudaEventDisableTiming);
    cudaEventCreateWithFlags(&eQK,  cudaEventDisableTiming);
    cudaEventCreateWithFlags(&eV,   cudaEventDisableTiming);
    cudaEventCreateWithFlags(&eBM,  cudaEventDisableTiming);
    cudaEventCreateWithFlags(&eWo,  cudaEventDisableTiming);
    cudaEventCreateWithFlags(&eW13, cudaEventDisableTiming);
    cudaEventCreateWithFlags(&eW2,  cudaEventDisableTiming);

    cudaEventRecord(eF, 0);
    cudaStreamWaitEvent(s1, eF, 0);

    cvt_h<<<1024, 256, 0, s1>>>(wq, cwqkv,                       (size_t)DIM_*DIM_/4);
    cvt_h<<<1024, 256, 0, s1>>>(wk, cwqkv + (size_t)DIM_*DIM_,   (size_t)DIM_*DIM_/4);
    cudaEventRecord(eQK, s1);
    cvt_h<<<1024, 256, 0, s1>>>(wv, cwqkv + (size_t)2*DIM_*DIM_, (size_t)DIM_*DIM_/4);
    cudaEventRecord(eV, s1);
    prep_bm<<<2048, 256, 0, s1>>>(bias, mask, bm16);
    cudaEventRecord(eBM, s1);
    cvt_h<<<1024, 256, 0, s1>>>(wo, cwo,                         (size_t)DIM_*DIM_/4);
    cudaEventRecord(eWo, s1);
    ilv_w13<<<(unsigned)((size_t)2*HID_*512/256), 256, 0, s1>>>(w1, w3, cw13);
    cudaEventRecord(eW13, s1);
    cvt_h<<<1024, 256, 0, s1>>>(w2, cw2,                         (size_t)DIM_*HID_/4);
    cudaEventRecord(eW2, s1);

    // ---- mainline (default stream) ----
    rmsnorm_k<<<M_, 256>>>(x, anw, h);
    // qk: [M, 4096] = h @ [wq;wk]^T, q cols pre-scaled
    cudaStreamWaitEvent(0, eQK, 0);
    mm_h<256><<<dim3(2*DIM_/256, M_/128), 256, SMH>>>(
        h, cwqkv, qkv, nullptr, DIM_, DIM_, DIM_, 2*DIM_, 5);
    // vt: [2048 d, 4096 tokens] = wv @ h^T (transposed-V GEMM)
    cudaStreamWaitEvent(0, eV, 0);
    mm_h<256><<<dim3(M_/256, DIM_/128), 256, SMH>>>(
        cwqkv + (size_t)2*DIM_*DIM_, h, vt, nullptr, DIM_, DIM_, DIM_, M_, 1);
    cudaStreamWaitEvent(0, eBM, 0);
    flash_k<<<dim3(S_/128, B_*NH_), 256, FL_SMEM>>>();
    cudaStreamWaitEvent(0, eWo, 0);
    mm_h<256><<<dim3(DIM_/256, M_/128), 256, SMH>>>(
        att, cwo, h1, x, DIM_, DIM_, DIM_, DIM_, 2);

    // --- FFN ---
    rmsnorm_k<<<M_, 256>>>(h1, fnw, f);
    cudaStreamWaitEvent(0, eW13, 0);
    mm_h<256><<<dim3(2*HID_/256, M_/128), 256, SMH>>>(
        f, cw13, ff, nullptr, DIM_, DIM_, DIM_, HID_, 4);
    cudaStreamWaitEvent(0, eW2, 0);
    mm_h<256><<<dim3(DIM_/256, M_/128), 256, SMH>>>(
        ff, cw2, out, h1, HID_, HID_, HID_, DIM_, 2);
}